// round 2
// baseline (speedup 1.0000x reference)
#include <cuda_runtime.h>
#include <cstdint>
#include <cstddef>

#define NEDGES  1600000
#define NNODES  100000
#define OUTD    64
#define KD      128
#define TILE    64
#define THREADS 128
#define ASTRIDE 132   // 128 + 4 pad: conflict-free column reads, float4-aligned rows

// Device scratch (no cudaMalloc allowed).
__device__ float g_agg[(size_t)NNODES * OUTD];
__device__ int   g_src[NEDGES];
__device__ int   g_dst[NEDGES];
__device__ int   g_batch[NNODES];

// ---------- packed fp32x2 helpers (Blackwell FFMA2 path, PTX-only) ----------
__device__ __forceinline__ unsigned long long pack2(float a) {
    unsigned long long r;
    asm("mov.b64 %0, {%1, %1};" : "=l"(r) : "r"(__float_as_uint(a)));
    return r;
}
__device__ __forceinline__ void fma2(unsigned long long& acc,
                                     unsigned long long a, unsigned long long b) {
    asm("fma.rn.f32x2 %0, %1, %2, %0;" : "+l"(acc) : "l"(a), "l"(b));
}
__device__ __forceinline__ float f2lo(unsigned long long v) { return __uint_as_float((unsigned)v); }
__device__ __forceinline__ float f2hi(unsigned long long v) { return __uint_as_float((unsigned)(v >> 32)); }

// ------------------- dtype-agnostic index conversion + agg zero -------------------
// JAX with x64 disabled silently turns int64 into int32; detect which layout the
// buffer actually has by probing the first 8 entries interpreted as int64.
__device__ __forceinline__ bool detect_is64(const long long* e64) {
    bool ok = true;
    #pragma unroll
    for (int i = 0; i < 8; i++)
        ok &= ((unsigned long long)e64[i] < (unsigned long long)NNODES);
    return ok;
}

__global__ void cvt_kernel(const void* ei_raw, const void* batch_raw) {
    const bool is64 = detect_is64((const long long*)ei_raw);
    const long long* e64 = (const long long*)ei_raw;
    const int*       e32 = (const int*)ei_raw;
    const long long* b64 = (const long long*)batch_raw;
    const int*       b32 = (const int*)batch_raw;

    const int i0 = blockIdx.x * blockDim.x + threadIdx.x;
    const int stride = gridDim.x * blockDim.x;
    for (int e = i0; e < NEDGES; e += stride) {
        g_src[e] = is64 ? (int)e64[e]          : e32[e];
        g_dst[e] = is64 ? (int)e64[NEDGES + e] : e32[NEDGES + e];
    }
    for (int n = i0; n < NNODES; n += stride)
        g_batch[n] = is64 ? (int)b64[n] : b32[n];

    // zero the aggregation scratch in the same pass
    float4* p = (float4*)g_agg;
    const int nz = NNODES * OUTD / 4;
    float4 z = make_float4(0.f, 0.f, 0.f, 0.f);
    for (int i = i0; i < nz; i += stride) p[i] = z;
}

// ------------------------------- edge MLP + scatter -------------------------------
// Per block: 64 edges x 64 outputs, K=128. A gathered to smem, W1 in smem.
// Thread: 2 edges x 16 outputs, f32x2 accumulators. Epilogue: bias+ReLU+red.v4.
__global__ void __launch_bounds__(THREADS) edge_kernel(
    const float* __restrict__ x, const float* __restrict__ ea,
    const float* __restrict__ u, const float* __restrict__ W1,
    const float* __restrict__ b1)
{
    extern __shared__ float smem[];
    float* As    = smem;                       // TILE*ASTRIDE
    float* Ws    = As + TILE * ASTRIDE;        // KD*OUTD
    float* sb    = Ws + KD * OUTD;             // OUTD
    int*   sDest = (int*)(sb + OUTD);          // TILE
    int*   sSrc  = sDest + TILE;               // TILE
    int*   sB    = sSrc + TILE;                // TILE

    const int tid = threadIdx.x;
    const long long e0base = (long long)blockIdx.x * TILE;

    if (tid < TILE) {
        int e = (int)e0base + tid;
        int s = g_src[e];
        sSrc[tid]  = s;
        sDest[tid] = g_dst[e];
        sB[tid]    = g_batch[s];
    }
    if (tid < OUTD) sb[tid] = b1[tid];

    {   // stage W1: 8192 floats = 2048 float4
        const float4* W4 = (const float4*)W1;
        float4* Ws4 = (float4*)Ws;
        #pragma unroll
        for (int i = 0; i < (KD * OUTD / 4) / THREADS; i++)
            Ws4[tid + i * THREADS] = W4[tid + i * THREADS];
    }
    __syncthreads();   // indices visible before gather

    {   // gather A: per row, segs 0-7 x[dest], 8-15 x[src], 16-23 edge_attr, 24-31 u[batch[src]]
        const float4* x4  = (const float4*)x;
        const float4* ea4 = (const float4*)ea;
        const float4* u4  = (const float4*)u;
        #pragma unroll
        for (int it = 0; it < (TILE * 32) / THREADS; it++) {
            int idx = tid + it * THREADS;
            int r = idx >> 5, seg = idx & 31;
            int q = seg >> 3, f = seg & 7;
            float4 v;
            if (q == 0)      v = x4[(size_t)sDest[r] * 8 + f];
            else if (q == 1) v = x4[(size_t)sSrc[r] * 8 + f];
            else if (q == 2) v = ea4[(e0base + r) * 8 + f];
            else             v = u4[(size_t)sB[r] * 8 + f];
            *(float4*)&As[r * ASTRIDE + seg * 4] = v;
        }
    }
    __syncthreads();

    const int pair = tid >> 2;
    const int j0 = (tid & 3) * 16;
    const float* A0 = As + (2 * pair) * ASTRIDE;
    const float* A1 = A0 + ASTRIDE;

    unsigned long long acc0[8], acc1[8];
    #pragma unroll
    for (int i = 0; i < 8; i++) { acc0[i] = 0ULL; acc1[i] = 0ULL; }

    #pragma unroll 8
    for (int k = 0; k < KD; k++) {
        unsigned long long a0 = pack2(A0[k]);
        unsigned long long a1 = pack2(A1[k]);
        const ulonglong2* w = (const ulonglong2*)&Ws[k * OUTD + j0];
        #pragma unroll
        for (int i = 0; i < 4; i++) {
            ulonglong2 wv = w[i];            // 4 weights as 2 packed pairs
            fma2(acc0[2 * i],     a0, wv.x);
            fma2(acc0[2 * i + 1], a0, wv.y);
            fma2(acc1[2 * i],     a1, wv.x);
            fma2(acc1[2 * i + 1], a1, wv.y);
        }
    }

    #pragma unroll
    for (int ee = 0; ee < 2; ee++) {
        unsigned long long* acc = ee ? acc1 : acc0;
        int d = sDest[2 * pair + ee];
        float* base = g_agg + (size_t)d * OUTD + j0;
        #pragma unroll
        for (int i = 0; i < 4; i++) {
            float v0 = fmaxf(f2lo(acc[2 * i])     + sb[j0 + 4 * i + 0], 0.f);
            float v1 = fmaxf(f2hi(acc[2 * i])     + sb[j0 + 4 * i + 1], 0.f);
            float v2 = fmaxf(f2lo(acc[2 * i + 1]) + sb[j0 + 4 * i + 2], 0.f);
            float v3 = fmaxf(f2hi(acc[2 * i + 1]) + sb[j0 + 4 * i + 3], 0.f);
            asm volatile("red.global.add.v4.f32 [%0], {%1,%2,%3,%4};"
                         :: "l"(base + 4 * i), "f"(v0), "f"(v1), "f"(v2), "f"(v3)
                         : "memory");
        }
    }
}

// --------------------------------- node MLP ---------------------------------
__global__ void __launch_bounds__(THREADS) node_kernel(
    const float* __restrict__ x, const float* __restrict__ u,
    const float* __restrict__ W2, const float* __restrict__ b2,
    float* __restrict__ out)
{
    extern __shared__ float smem[];
    float* As = smem;
    float* Ws = As + TILE * ASTRIDE;
    float* sb = Ws + KD * OUTD;

    const int tid = threadIdx.x;
    const long long n0 = (long long)blockIdx.x * TILE;

    if (tid < OUTD) sb[tid] = b2[tid];
    {
        const float4* W4 = (const float4*)W2;
        float4* Ws4 = (float4*)Ws;
        #pragma unroll
        for (int i = 0; i < (KD * OUTD / 4) / THREADS; i++)
            Ws4[tid + i * THREADS] = W4[tid + i * THREADS];
    }

    {   // gather A: segs 0-7 x[n], 8-23 agg[n], 24-31 u[batch[n]]
        const float4* x4 = (const float4*)x;
        const float4* u4 = (const float4*)u;
        const float4* agg4 = (const float4*)g_agg;
        #pragma unroll
        for (int it = 0; it < (TILE * 32) / THREADS; it++) {
            int idx = tid + it * THREADS;
            int r = idx >> 5, seg = idx & 31;
            long long n = n0 + r;
            if (n >= NNODES) n = NNODES - 1;   // safe clamp for tail block
            float4 v;
            if (seg < 8)       v = x4[(size_t)n * 8 + seg];
            else if (seg < 24) v = agg4[(size_t)n * 16 + (seg - 8)];
            else               v = u4[(size_t)g_batch[n] * 8 + (seg - 24)];
            *(float4*)&As[r * ASTRIDE + seg * 4] = v;
        }
    }
    __syncthreads();

    const int pair = tid >> 2;
    const int j0 = (tid & 3) * 16;
    const float* A0 = As + (2 * pair) * ASTRIDE;
    const float* A1 = A0 + ASTRIDE;

    unsigned long long acc0[8], acc1[8];
    #pragma unroll
    for (int i = 0; i < 8; i++) { acc0[i] = 0ULL; acc1[i] = 0ULL; }

    #pragma unroll 8
    for (int k = 0; k < KD; k++) {
        unsigned long long a0 = pack2(A0[k]);
        unsigned long long a1 = pack2(A1[k]);
        const ulonglong2* w = (const ulonglong2*)&Ws[k * OUTD + j0];
        #pragma unroll
        for (int i = 0; i < 4; i++) {
            ulonglong2 wv = w[i];
            fma2(acc0[2 * i],     a0, wv.x);
            fma2(acc0[2 * i + 1], a0, wv.y);
            fma2(acc1[2 * i],     a1, wv.x);
            fma2(acc1[2 * i + 1], a1, wv.y);
        }
    }

    #pragma unroll
    for (int ee = 0; ee < 2; ee++) {
        unsigned long long* acc = ee ? acc1 : acc0;
        long long n = n0 + 2 * pair + ee;
        if (n < NNODES) {
            float4* ob = (float4*)(out + (size_t)n * OUTD + j0);
            #pragma unroll
            for (int i = 0; i < 4; i++) {
                float4 v;
                v.x = fmaxf(f2lo(acc[2 * i])     + sb[j0 + 4 * i + 0], 0.f);
                v.y = fmaxf(f2hi(acc[2 * i])     + sb[j0 + 4 * i + 1], 0.f);
                v.z = fmaxf(f2lo(acc[2 * i + 1]) + sb[j0 + 4 * i + 2], 0.f);
                v.w = fmaxf(f2hi(acc[2 * i + 1]) + sb[j0 + 4 * i + 3], 0.f);
                ob[i] = v;
            }
        }
    }
}

// --------------------------------- launcher ---------------------------------
extern "C" void kernel_launch(void* const* d_in, const int* in_sizes, int n_in,
                              void* d_out, int out_size) {
    const float* x     = (const float*)d_in[0];
    const void*  ei    = d_in[1];
    const float* ea    = (const float*)d_in[2];
    const float* u     = (const float*)d_in[3];
    const void*  batch = d_in[4];
    const float* W1    = (const float*)d_in[5];
    const float* b1    = (const float*)d_in[6];
    const float* W2    = (const float*)d_in[7];
    const float* b2    = (const float*)d_in[8];
    float* out = (float*)d_out;

    const int smem1 = (TILE * ASTRIDE + KD * OUTD + OUTD) * 4 + 3 * TILE * 4;
    const int smem2 = (TILE * ASTRIDE + KD * OUTD + OUTD) * 4;
    cudaFuncSetAttribute(edge_kernel, cudaFuncAttributeMaxDynamicSharedMemorySize, smem1);
    cudaFuncSetAttribute(node_kernel, cudaFuncAttributeMaxDynamicSharedMemorySize, smem2);

    cvt_kernel<<<1184, 256>>>(ei, batch);
    edge_kernel<<<NEDGES / TILE, THREADS, smem1>>>(x, ea, u, W1, b1);
    node_kernel<<<(NNODES + TILE - 1) / TILE, THREADS, smem2>>>(x, u, W2, b2, out);
}

// round 4
// speedup vs baseline: 1.6265x; 1.6265x over previous
#include <cuda_runtime.h>
#include <cuda_bf16.h>
#include <cstdint>
#include <cstddef>

#define NEDGES  1600000
#define NNODES  100000
#define OUTD    64
#define MTILE   128
#define THREADS 128
#define EDGE_BLOCKS (NEDGES / MTILE)                 // 12500
#define NODE_BLOCKS ((NNODES + MTILE - 1) / MTILE)   // 782

// ---- smem layout (bytes) ----
#define SM_BIAS 0        // 64 floats
#define SM_DST  256      // 128 int
#define SM_SRC  768      // 128 int
#define SM_BB   1280     // 128 int
#define SM_AHI  2048     // 128x128 bf16 (32KB), XOR-swizzled rows of 256B
#define SM_ALO  (SM_AHI + 32768)
#define SM_BHI  (SM_ALO + 32768)   // 64x128 bf16 (16KB) = B^T rows
#define SM_BLO  (SM_BHI + 16384)
#define SM_SZ   (SM_BLO + 16384)   // 100352

// ---- device scratch ----
__device__ float g_agg[(size_t)NNODES * OUTD];
__device__ int   g_src[NEDGES];
__device__ int   g_dst[NEDGES];
__device__ int   g_batch[NNODES];
__device__ __align__(16) unsigned char g_w1hi[16384];
__device__ __align__(16) unsigned char g_w1lo[16384];
__device__ __align__(16) unsigned char g_w2hi[16384];
__device__ __align__(16) unsigned char g_w2lo[16384];

// ================= helpers =================
__device__ __forceinline__ uint32_t smem_u32(const void* p) {
    uint32_t a;
    asm("{ .reg .u64 t; cvta.to.shared.u64 t, %1; cvt.u32.u64 %0, t; }" : "=r"(a) : "l"(p));
    return a;
}
// split fp32 pair (adjacent K) into packed bf16x2 hi and lo words
__device__ __forceinline__ void split_pack(float a, float b, uint32_t& hi, uint32_t& lo) {
    __nv_bfloat16 ah = __float2bfloat16(a), bh = __float2bfloat16(b);
    float al = a - __bfloat162float(ah);
    float bl = b - __bfloat162float(bh);
    hi = (uint32_t)__bfloat16_as_ushort(ah) | ((uint32_t)__bfloat16_as_ushort(bh) << 16);
    lo = (uint32_t)__bfloat16_as_ushort(__float2bfloat16(al))
       | ((uint32_t)__bfloat16_as_ushort(__float2bfloat16(bl)) << 16);
}
// swizzled byte offset inside a [row][64-word] tile: word ^= (row&7)<<2
__device__ __forceinline__ uint32_t swz(int r, uint32_t w) {
    return (uint32_t)r * 256u + ((w ^ (uint32_t)((r & 7) << 2)) << 2);
}
__device__ __forceinline__ void stash4(char* smem, int r, int c, float4 v) {
    uint32_t h0, l0, h1, l1;
    split_pack(v.x, v.y, h0, l0);
    split_pack(v.z, v.w, h1, l1);
    uint32_t w0 = (uint32_t)(c >> 1);          // c multiple of 4 -> w0 even
    uint32_t o0 = swz(r, w0), o1 = swz(r, w0 + 1);
    *(uint32_t*)(smem + SM_AHI + o0) = h0;
    *(uint32_t*)(smem + SM_AHI + o1) = h1;
    *(uint32_t*)(smem + SM_ALO + o0) = l0;
    *(uint32_t*)(smem + SM_ALO + o1) = l1;
}
__device__ __forceinline__ void ldsm4(uint32_t addr, uint32_t* r) {
    asm volatile("ldmatrix.sync.aligned.m8n8.x4.shared.b16 {%0,%1,%2,%3}, [%4];"
                 : "=r"(r[0]), "=r"(r[1]), "=r"(r[2]), "=r"(r[3]) : "r"(addr));
}
__device__ __forceinline__ void mma_bf16(float* d, const uint32_t* a, uint32_t b0, uint32_t b1) {
    asm volatile(
        "mma.sync.aligned.m16n8k16.row.col.f32.bf16.bf16.f32 "
        "{%0,%1,%2,%3},{%4,%5,%6,%7},{%8,%9},{%0,%1,%2,%3};"
        : "+f"(d[0]), "+f"(d[1]), "+f"(d[2]), "+f"(d[3])
        : "r"(a[0]), "r"(a[1]), "r"(a[2]), "r"(a[3]), "r"(b0), "r"(b1));
}
__device__ __forceinline__ void red2(float* p, float v0, float v1) {
    asm volatile("red.global.add.v2.f32 [%0], {%1,%2};"
                 :: "l"(p), "f"(v0), "f"(v1) : "memory");
}

// ==================== prep ====================
__device__ __forceinline__ bool detect_is64(const long long* e64) {
    bool ok = true;
    #pragma unroll
    for (int i = 0; i < 8; i++)
        ok &= ((unsigned long long)e64[i] < (unsigned long long)NNODES);
    return ok;
}
// pack W[k][n] (k in pairs) into B^T rows [n][kword], swizzled — directly ldmatrix-ready
__device__ __forceinline__ void pack_w(unsigned char* hi, unsigned char* lo,
                                       const float* W, int n, int k) {
    float a = W[(size_t)k * OUTD + n];
    float b = W[(size_t)(k + 1) * OUTD + n];
    uint32_t h, l;
    split_pack(a, b, h, l);
    uint32_t off = swz(n, (uint32_t)(k >> 1));
    *(uint32_t*)(hi + off) = h;
    *(uint32_t*)(lo + off) = l;
}

__global__ void prep_kernel(const void* ei_raw, const void* batch_raw,
                            const float* __restrict__ W1, const float* __restrict__ W2) {
    const bool is64 = detect_is64((const long long*)ei_raw);
    const long long* e64 = (const long long*)ei_raw;
    const int*       e32 = (const int*)ei_raw;
    const long long* b64 = (const long long*)batch_raw;
    const int*       b32 = (const int*)batch_raw;

    const int i0 = blockIdx.x * blockDim.x + threadIdx.x;
    const int stride = gridDim.x * blockDim.x;

    for (int e = i0; e < NEDGES; e += stride) {
        g_src[e] = is64 ? (int)e64[e]          : e32[e];
        g_dst[e] = is64 ? (int)e64[NEDGES + e] : e32[NEDGES + e];
    }
    for (int n = i0; n < NNODES; n += stride)
        g_batch[n] = is64 ? (int)b64[n] : b32[n];

    float4* p = (float4*)g_agg;
    const int nz = NNODES * OUTD / 4;
    float4 z = make_float4(0.f, 0.f, 0.f, 0.f);
    for (int i = i0; i < nz; i += stride) p[i] = z;

    for (int q = i0; q < 4096; q += stride) {   // 64 n x 64 k-pairs
        int n = q >> 6, k = (q & 63) << 1;
        pack_w(g_w1hi, g_w1lo, W1, n, k);
        pack_w(g_w2hi, g_w2lo, W2, n, k);
    }
}

// ==================== shared pieces ====================
__device__ __forceinline__ void copy_B(char* smem, const unsigned char* whi,
                                       const unsigned char* wlo, int tid) {
    const float4* h4 = (const float4*)whi;
    const float4* l4 = (const float4*)wlo;
    float4* dh = (float4*)(smem + SM_BHI);
    float4* dl = (float4*)(smem + SM_BLO);
    #pragma unroll
    for (int i = 0; i < 1024 / THREADS; i++) {
        dh[tid + i * THREADS] = h4[tid + i * THREADS];
        dl[tid + i * THREADS] = l4[tid + i * THREADS];
    }
}

// 3-pass split GEMM: acc[mt][ntile][4] += A(128xK128) * B^T(64xK128)
__device__ __forceinline__ void gemm_core(uint32_t sb, int warp, int lane,
                                          float acc[2][8][4]) {
    const int j  = lane >> 3;
    const int rr = lane & 7;
    const uint32_t xo = (uint32_t)(rr << 2);
    const int rowA = warp * 32 + ((j & 1) << 3) + rr;   // +16 for mt=1
    const int rowB = ((j & 1) << 3) + rr;               // +16 per n-pair
    const uint32_t ksg = (uint32_t)((j >> 1) << 2);     // word offset 0 or 4

    #pragma unroll
    for (int ks = 0; ks < 8; ks++) {
        const uint32_t byte = (((uint32_t)(ks * 8) + ksg) ^ xo) << 2;
        uint32_t ah0[4], ah1[4], al0[4], al1[4];
        const uint32_t aAddr = sb + SM_AHI + (uint32_t)rowA * 256 + byte;
        ldsm4(aAddr,                 ah0);
        ldsm4(aAddr + 16 * 256,      ah1);
        ldsm4(aAddr + 32768,         al0);
        ldsm4(aAddr + 32768 + 16*256, al1);
        #pragma unroll
        for (int np = 0; np < 4; np++) {
            uint32_t bh[4], bl[4];
            const uint32_t bAddr = sb + SM_BHI + (uint32_t)(rowB + np * 16) * 256 + byte;
            ldsm4(bAddr,          bh);
            ldsm4(bAddr + 16384,  bl);
            // n-tile 2np uses regs {0,2}; n-tile 2np+1 uses {1,3}
            mma_bf16(acc[0][2*np],   ah0, bh[0], bh[2]);
            mma_bf16(acc[0][2*np],   ah0, bl[0], bl[2]);
            mma_bf16(acc[0][2*np],   al0, bh[0], bh[2]);
            mma_bf16(acc[0][2*np+1], ah0, bh[1], bh[3]);
            mma_bf16(acc[0][2*np+1], ah0, bl[1], bl[3]);
            mma_bf16(acc[0][2*np+1], al0, bh[1], bh[3]);
            mma_bf16(acc[1][2*np],   ah1, bh[0], bh[2]);
            mma_bf16(acc[1][2*np],   ah1, bl[0], bl[2]);
            mma_bf16(acc[1][2*np],   al1, bh[0], bh[2]);
            mma_bf16(acc[1][2*np+1], ah1, bh[1], bh[3]);
            mma_bf16(acc[1][2*np+1], ah1, bl[1], bl[3]);
            mma_bf16(acc[1][2*np+1], al1, bh[1], bh[3]);
        }
    }
}

// ==================== edge kernel ====================
__global__ void __launch_bounds__(THREADS) edge_kernel(
    const float* __restrict__ x, const float* __restrict__ ea,
    const float* __restrict__ u, const float* __restrict__ b1)
{
    extern __shared__ char smem[];
    const uint32_t sb = smem_u32(smem);
    const int tid = threadIdx.x;
    const long long e0 = (long long)blockIdx.x * MTILE;

    int* sDst = (int*)(smem + SM_DST);
    int* sSrc = (int*)(smem + SM_SRC);
    int* sBB  = (int*)(smem + SM_BB);

    {   // indices: thread = row
        int e = (int)e0 + tid;
        int s = g_src[e];
        sSrc[tid] = s;
        sDst[tid] = g_dst[e];
        sBB[tid]  = g_batch[s];
    }
    if (tid < OUTD) ((float*)(smem + SM_BIAS))[tid] = b1[tid];
    copy_B(smem, g_w1hi, g_w1lo, tid);
    __syncthreads();

    {   // gather: coalesced (row, seg) decomposition
        const float4* x4  = (const float4*)x;
        const float4* ea4 = (const float4*)ea;
        const float4* u4  = (const float4*)u;
        #pragma unroll
        for (int it = 0; it < 32; it++) {
            int idx = tid + it * THREADS;
            int r = idx >> 5, seg = idx & 31;
            int q = seg >> 3, f = seg & 7;
            float4 v;
            if (q == 0)      v = x4[(size_t)sDst[r] * 8 + f];
            else if (q == 1) v = x4[(size_t)sSrc[r] * 8 + f];
            else if (q == 2) v = ea4[(e0 + r) * 8 + f];
            else             v = u4[(size_t)sBB[r] * 8 + f];
            stash4(smem, r, seg * 4, v);
        }
    }
    __syncthreads();

    const int lane = tid & 31, warp = tid >> 5;
    float acc[2][8][4];
    #pragma unroll
    for (int a = 0; a < 2; a++)
        #pragma unroll
        for (int b = 0; b < 8; b++)
            #pragma unroll
            for (int c = 0; c < 4; c++) acc[a][b][c] = 0.f;

    gemm_core(sb, warp, lane, acc);

    {   // bias + relu + scatter
        const float* bias = (const float*)(smem + SM_BIAS);
        #pragma unroll
        for (int mt = 0; mt < 2; mt++) {
            int ra = warp * 32 + mt * 16 + (lane >> 2);
            int rb = ra + 8;
            int da = sDst[ra], db = sDst[rb];
            #pragma unroll
            for (int j = 0; j < 8; j++) {
                int c = j * 8 + (lane & 3) * 2;
                float bb0 = bias[c], bb1 = bias[c + 1];
                red2(g_agg + (size_t)da * OUTD + c,
                     fmaxf(acc[mt][j][0] + bb0, 0.f),
                     fmaxf(acc[mt][j][1] + bb1, 0.f));
                red2(g_agg + (size_t)db * OUTD + c,
                     fmaxf(acc[mt][j][2] + bb0, 0.f),
                     fmaxf(acc[mt][j][3] + bb1, 0.f));
            }
        }
    }
}

// ==================== node kernel ====================
__global__ void __launch_bounds__(THREADS) node_kernel(
    const float* __restrict__ x, const float* __restrict__ u,
    const float* __restrict__ b2, float* __restrict__ out)
{
    extern __shared__ char smem[];
    const uint32_t sb = smem_u32(smem);
    const int tid = threadIdx.x;
    const long long n0 = (long long)blockIdx.x * MTILE;

    int* sBB = (int*)(smem + SM_BB);
    {
        long long nn = n0 + tid;
        if (nn >= NNODES) nn = NNODES - 1;
        sBB[tid] = g_batch[nn];
    }
    if (tid < OUTD) ((float*)(smem + SM_BIAS))[tid] = b2[tid];
    copy_B(smem, g_w2hi, g_w2lo, tid);
    __syncthreads();

    {   // gather: x (segs 0-7), agg (8-23), u (24-31)
        const float4* x4 = (const float4*)x;
        const float4* u4 = (const float4*)u;
        const float4* agg4 = (const float4*)g_agg;
        #pragma unroll
        for (int it = 0; it < 32; it++) {
            int idx = tid + it * THREADS;
            int r = idx >> 5, seg = idx & 31;
            long long nn = n0 + r;
            if (nn >= NNODES) nn = NNODES - 1;
            float4 v;
            if (seg < 8)       v = x4[(size_t)nn * 8 + seg];
            else if (seg < 24) v = agg4[(size_t)nn * 16 + (seg - 8)];
            else               v = u4[(size_t)sBB[r] * 8 + (seg - 24)];
            stash4(smem, r, seg * 4, v);
        }
    }
    __syncthreads();

    const int lane = tid & 31, warp = tid >> 5;
    float acc[2][8][4];
    #pragma unroll
    for (int a = 0; a < 2; a++)
        #pragma unroll
        for (int b = 0; b < 8; b++)
            #pragma unroll
            for (int c = 0; c < 4; c++) acc[a][b][c] = 0.f;

    gemm_core(sb, warp, lane, acc);

    {   // bias + relu + store
        const float* bias = (const float*)(smem + SM_BIAS);
        #pragma unroll
        for (int mt = 0; mt < 2; mt++) {
            long long ra = n0 + warp * 32 + mt * 16 + (lane >> 2);
            long long rb = ra + 8;
            #pragma unroll
            for (int j = 0; j < 8; j++) {
                int c = j * 8 + (lane & 3) * 2;
                float bb0 = bias[c], bb1 = bias[c + 1];
                if (ra < NNODES)
                    *(float2*)(out + (size_t)ra * OUTD + c) =
                        make_float2(fmaxf(acc[mt][j][0] + bb0, 0.f),
                                    fmaxf(acc[mt][j][1] + bb1, 0.f));
                if (rb < NNODES)
                    *(float2*)(out + (size_t)rb * OUTD + c) =
                        make_float2(fmaxf(acc[mt][j][2] + bb0, 0.f),
                                    fmaxf(acc[mt][j][3] + bb1, 0.f));
            }
        }
    }
}

// ==================== launcher ====================
extern "C" void kernel_launch(void* const* d_in, const int* in_sizes, int n_in,
                              void* d_out, int out_size) {
    const float* x     = (const float*)d_in[0];
    const void*  ei    = d_in[1];
    const float* ea    = (const float*)d_in[2];
    const float* u     = (const float*)d_in[3];
    const void*  batch = d_in[4];
    const float* W1    = (const float*)d_in[5];
    const float* b1    = (const float*)d_in[6];
    const float* W2    = (const float*)d_in[7];
    const float* b2    = (const float*)d_in[8];
    float* out = (float*)d_out;

    cudaFuncSetAttribute(edge_kernel, cudaFuncAttributeMaxDynamicSharedMemorySize, SM_SZ);
    cudaFuncSetAttribute(node_kernel, cudaFuncAttributeMaxDynamicSharedMemorySize, SM_SZ);

    prep_kernel<<<1480, 256>>>(ei, batch, W1, W2);
    edge_kernel<<<EDGE_BLOCKS, THREADS, SM_SZ>>>(x, ea, u, b1);
    node_kernel<<<NODE_BLOCKS, THREADS, SM_SZ>>>(x, u, b2, out);
}

// round 5
// speedup vs baseline: 1.7863x; 1.0983x over previous
#include <cuda_runtime.h>
#include <cuda_bf16.h>
#include <cstdint>
#include <cstddef>

#define NEDGES  1600000
#define NNODES  100000
#define OUTD    64
#define MTILE   128
#define THREADS 128
#define EDGE_BLOCKS (NEDGES / MTILE)                 // 12500
#define NODE_BLOCKS ((NNODES + MTILE - 1) / MTILE)   // 782

// ---- smem layout (bytes) ----
#define SM_BIAS 0        // 64 floats
#define SM_DST  256      // 128 int
#define SM_SRC  768      // 128 int
#define SM_BB   1280     // 128 int
#define SM_AHI  2048     // 128x128 bf16 (32KB), XOR-swizzled rows of 256B
#define SM_ALO  (SM_AHI + 32768)
#define SM_BHI  (SM_ALO + 32768)   // 64x128 bf16 (16KB) = B^T rows (col-permuted)
#define SM_BLO  (SM_BHI + 16384)
#define SM_SZ   (SM_BLO + 16384)   // 100352

// ---- device scratch ----
__device__ float g_agg[(size_t)NNODES * OUTD];
__device__ int   g_src[NEDGES];
__device__ int   g_dst[NEDGES];
__device__ int   g_batch[NNODES];
__device__ __align__(16) unsigned char g_w1hi[16384];
__device__ __align__(16) unsigned char g_w1lo[16384];
__device__ __align__(16) unsigned char g_w2hi[16384];
__device__ __align__(16) unsigned char g_w2lo[16384];

// ================= helpers =================
__device__ __forceinline__ uint32_t smem_u32(const void* p) {
    uint32_t a;
    asm("{ .reg .u64 t; cvta.to.shared.u64 t, %1; cvt.u32.u64 %0, t; }" : "=r"(a) : "l"(p));
    return a;
}
// split fp32 pair (adjacent K) into packed bf16x2 hi and lo words (low half = even k)
__device__ __forceinline__ void split_pack(float a, float b, uint32_t& hi, uint32_t& lo) {
    uint32_t h;
    asm("cvt.rn.bf16x2.f32 %0, %1, %2;" : "=r"(h) : "f"(b), "f"(a));
    float ha = __uint_as_float(h << 16);
    float hb = __uint_as_float(h & 0xFFFF0000u);
    float la = a - ha, lb = b - hb;
    uint32_t l;
    asm("cvt.rn.bf16x2.f32 %0, %1, %2;" : "=r"(l) : "f"(lb), "f"(la));
    hi = h; lo = l;
}
// swizzled byte offset inside a [row][64-word] tile: word ^= (row&7)<<2
__device__ __forceinline__ uint32_t swz(int r, uint32_t w) {
    return (uint32_t)r * 256u + ((w ^ (uint32_t)((r & 7) << 2)) << 2);
}
__device__ __forceinline__ void stash4(char* smem, int r, int c, float4 v) {
    uint32_t h0, l0, h1, l1;
    split_pack(v.x, v.y, h0, l0);
    split_pack(v.z, v.w, h1, l1);
    uint32_t w0 = (uint32_t)(c >> 1);          // c multiple of 4 -> w0 even
    uint32_t o0 = swz(r, w0), o1 = swz(r, w0 + 1);
    *(uint32_t*)(smem + SM_AHI + o0) = h0;
    *(uint32_t*)(smem + SM_AHI + o1) = h1;
    *(uint32_t*)(smem + SM_ALO + o0) = l0;
    *(uint32_t*)(smem + SM_ALO + o1) = l1;
}
__device__ __forceinline__ void ldsm4(uint32_t addr, uint32_t* r) {
    asm volatile("ldmatrix.sync.aligned.m8n8.x4.shared.b16 {%0,%1,%2,%3}, [%4];"
                 : "=r"(r[0]), "=r"(r[1]), "=r"(r[2]), "=r"(r[3]) : "r"(addr));
}
__device__ __forceinline__ void mma_bf16(float* d, const uint32_t* a, uint32_t b0, uint32_t b1) {
    asm volatile(
        "mma.sync.aligned.m16n8k16.row.col.f32.bf16.bf16.f32 "
        "{%0,%1,%2,%3},{%4,%5,%6,%7},{%8,%9},{%0,%1,%2,%3};"
        : "+f"(d[0]), "+f"(d[1]), "+f"(d[2]), "+f"(d[3])
        : "r"(a[0]), "r"(a[1]), "r"(a[2]), "r"(a[3]), "r"(b0), "r"(b1));
}
__device__ __forceinline__ void red4(float* p, float v0, float v1, float v2, float v3) {
    asm volatile("red.global.add.v4.f32 [%0], {%1,%2,%3,%4};"
                 :: "l"(p), "f"(v0), "f"(v1), "f"(v2), "f"(v3) : "memory");
}

// column permutation: physical B^T row n holds weights of logical output column perm_col(n).
// Within each 16-row group p = n&15: logical = 4*((p&7)>>1) + 2*(p>>3) + (p&1).
// This makes each thread's 4 values per n-tile-pair logically consecutive -> red.v4 / float4.
__device__ __host__ __forceinline__ int perm_col(int n) {
    int p = n & 15;
    return (n & ~15) + ((p & 7) >> 1) * 4 + ((p >> 3) << 1) + (p & 1);
}

// ==================== prep ====================
__device__ __forceinline__ bool detect_is64(const long long* e64) {
    bool ok = true;
    #pragma unroll
    for (int i = 0; i < 8; i++)
        ok &= ((unsigned long long)e64[i] < (unsigned long long)NNODES);
    return ok;
}
__device__ __forceinline__ void pack_w(unsigned char* hi, unsigned char* lo,
                                       const float* W, int n, int k) {
    int l = perm_col(n);
    float a = W[(size_t)k * OUTD + l];
    float b = W[(size_t)(k + 1) * OUTD + l];
    uint32_t h, lw;
    split_pack(a, b, h, lw);
    uint32_t off = swz(n, (uint32_t)(k >> 1));
    *(uint32_t*)(hi + off) = h;
    *(uint32_t*)(lo + off) = lw;
}

__global__ void prep_kernel(const void* ei_raw, const void* batch_raw,
                            const float* __restrict__ W1, const float* __restrict__ W2) {
    const bool is64 = detect_is64((const long long*)ei_raw);
    const long long* e64 = (const long long*)ei_raw;
    const int*       e32 = (const int*)ei_raw;
    const long long* b64 = (const long long*)batch_raw;
    const int*       b32 = (const int*)batch_raw;

    const int i0 = blockIdx.x * blockDim.x + threadIdx.x;
    const int stride = gridDim.x * blockDim.x;

    for (int e = i0; e < NEDGES; e += stride) {
        g_src[e] = is64 ? (int)e64[e]          : e32[e];
        g_dst[e] = is64 ? (int)e64[NEDGES + e] : e32[NEDGES + e];
    }
    for (int n = i0; n < NNODES; n += stride)
        g_batch[n] = is64 ? (int)b64[n] : b32[n];

    float4* p = (float4*)g_agg;
    const int nz = NNODES * OUTD / 4;
    float4 z = make_float4(0.f, 0.f, 0.f, 0.f);
    for (int i = i0; i < nz; i += stride) p[i] = z;

    for (int q = i0; q < 4096; q += stride) {   // 64 n x 64 k-pairs
        int n = q >> 6, k = (q & 63) << 1;
        pack_w(g_w1hi, g_w1lo, W1, n, k);
        pack_w(g_w2hi, g_w2lo, W2, n, k);
    }
}

// ==================== shared pieces ====================
__device__ __forceinline__ void copy_B(char* smem, const unsigned char* whi,
                                       const unsigned char* wlo, int tid) {
    const float4* h4 = (const float4*)whi;
    const float4* l4 = (const float4*)wlo;
    float4* dh = (float4*)(smem + SM_BHI);
    float4* dl = (float4*)(smem + SM_BLO);
    #pragma unroll
    for (int i = 0; i < 1024 / THREADS; i++) {
        dh[tid + i * THREADS] = h4[tid + i * THREADS];
        dl[tid + i * THREADS] = l4[tid + i * THREADS];
    }
}

// init accumulators with bias (saves epilogue adds); col layout per perm_col scheme
__device__ __forceinline__ void init_acc(const float* bias, int lane, float acc[2][8][4]) {
    #pragma unroll
    for (int j = 0; j < 8; j++) {
        int c = (j >> 1) * 16 + (lane & 3) * 4 + (j & 1) * 2;
        float b0 = bias[c], b1 = bias[c + 1];
        acc[0][j][0] = b0; acc[0][j][1] = b1; acc[0][j][2] = b0; acc[0][j][3] = b1;
        acc[1][j][0] = b0; acc[1][j][1] = b1; acc[1][j][2] = b0; acc[1][j][3] = b1;
    }
}

// 3-pass split GEMM: acc[mt][ntile][4] += A(128xK128) * B^T(64xK128)
__device__ __forceinline__ void gemm_core(uint32_t sb, int warp, int lane,
                                          float acc[2][8][4]) {
    const int j  = lane >> 3;
    const int rr = lane & 7;
    const uint32_t xo = (uint32_t)(rr << 2);
    const int rowA = warp * 32 + ((j & 1) << 3) + rr;   // +16 for mt=1
    const int rowB = ((j & 1) << 3) + rr;               // +16 per n-pair
    const uint32_t ksg = (uint32_t)((j >> 1) << 2);     // word offset 0 or 4

    #pragma unroll
    for (int ks = 0; ks < 8; ks++) {
        const uint32_t byte = (((uint32_t)(ks * 8) + ksg) ^ xo) << 2;
        uint32_t ah0[4], ah1[4], al0[4], al1[4];
        const uint32_t aAddr = sb + SM_AHI + (uint32_t)rowA * 256 + byte;
        ldsm4(aAddr,                  ah0);
        ldsm4(aAddr + 16 * 256,       ah1);
        ldsm4(aAddr + 32768,          al0);
        ldsm4(aAddr + 32768 + 16*256, al1);
        #pragma unroll
        for (int np = 0; np < 4; np++) {
            uint32_t bh[4], bl[4];
            const uint32_t bAddr = sb + SM_BHI + (uint32_t)(rowB + np * 16) * 256 + byte;
            ldsm4(bAddr,          bh);
            ldsm4(bAddr + 16384,  bl);
            mma_bf16(acc[0][2*np],   ah0, bh[0], bh[2]);
            mma_bf16(acc[0][2*np],   ah0, bl[0], bl[2]);
            mma_bf16(acc[0][2*np],   al0, bh[0], bh[2]);
            mma_bf16(acc[0][2*np+1], ah0, bh[1], bh[3]);
            mma_bf16(acc[0][2*np+1], ah0, bl[1], bl[3]);
            mma_bf16(acc[0][2*np+1], al0, bh[1], bh[3]);
            mma_bf16(acc[1][2*np],   ah1, bh[0], bh[2]);
            mma_bf16(acc[1][2*np],   ah1, bl[0], bl[2]);
            mma_bf16(acc[1][2*np],   al1, bh[0], bh[2]);
            mma_bf16(acc[1][2*np+1], ah1, bh[1], bh[3]);
            mma_bf16(acc[1][2*np+1], ah1, bl[1], bl[3]);
            mma_bf16(acc[1][2*np+1], al1, bh[1], bh[3]);
        }
    }
}

// ==================== edge kernel ====================
__global__ void __launch_bounds__(THREADS) edge_kernel(
    const float* __restrict__ x, const float* __restrict__ ea,
    const float* __restrict__ u, const float* __restrict__ b1)
{
    extern __shared__ char smem[];
    const uint32_t sb = smem_u32(smem);
    const int tid = threadIdx.x;
    const long long e0 = (long long)blockIdx.x * MTILE;

    int* sDst = (int*)(smem + SM_DST);
    int* sSrc = (int*)(smem + SM_SRC);
    int* sBB  = (int*)(smem + SM_BB);

    {   // indices: thread = row
        int e = (int)e0 + tid;
        int s = g_src[e];
        sSrc[tid] = s;
        sDst[tid] = g_dst[e];
        sBB[tid]  = g_batch[s];
    }
    if (tid < OUTD) ((float*)(smem + SM_BIAS))[tid] = b1[tid];
    copy_B(smem, g_w1hi, g_w1lo, tid);
    __syncthreads();

    {   // gather: coalesced (row, seg) decomposition
        const float4* x4  = (const float4*)x;
        const float4* ea4 = (const float4*)ea;
        const float4* u4  = (const float4*)u;
        #pragma unroll
        for (int it = 0; it < 32; it++) {
            int idx = tid + it * THREADS;
            int r = idx >> 5, seg = idx & 31;
            int q = seg >> 3, f = seg & 7;
            float4 v;
            if (q == 0)      v = x4[(size_t)sDst[r] * 8 + f];
            else if (q == 1) v = x4[(size_t)sSrc[r] * 8 + f];
            else if (q == 2) v = ea4[(e0 + r) * 8 + f];
            else             v = u4[(size_t)sBB[r] * 8 + f];
            stash4(smem, r, seg * 4, v);
        }
    }
    __syncthreads();

    const int lane = tid & 31, warp = tid >> 5;
    float acc[2][8][4];
    init_acc((const float*)(smem + SM_BIAS), lane, acc);

    gemm_core(sb, warp, lane, acc);

    {   // relu + v4 scatter (bias already in acc)
        #pragma unroll
        for (int mt = 0; mt < 2; mt++) {
            int ra = warp * 32 + mt * 16 + (lane >> 2);
            int rb = ra + 8;
            float* pa = g_agg + (size_t)sDst[ra] * OUTD + (lane & 3) * 4;
            float* pb = g_agg + (size_t)sDst[rb] * OUTD + (lane & 3) * 4;
            #pragma unroll
            for (int np = 0; np < 4; np++) {
                red4(pa + np * 16,
                     fmaxf(acc[mt][2*np][0], 0.f),   fmaxf(acc[mt][2*np][1], 0.f),
                     fmaxf(acc[mt][2*np+1][0], 0.f), fmaxf(acc[mt][2*np+1][1], 0.f));
                red4(pb + np * 16,
                     fmaxf(acc[mt][2*np][2], 0.f),   fmaxf(acc[mt][2*np][3], 0.f),
                     fmaxf(acc[mt][2*np+1][2], 0.f), fmaxf(acc[mt][2*np+1][3], 0.f));
            }
        }
    }
}

// ==================== node kernel ====================
__global__ void __launch_bounds__(THREADS) node_kernel(
    const float* __restrict__ x, const float* __restrict__ u,
    const float* __restrict__ b2, float* __restrict__ out)
{
    extern __shared__ char smem[];
    const uint32_t sb = smem_u32(smem);
    const int tid = threadIdx.x;
    const long long n0 = (long long)blockIdx.x * MTILE;

    int* sBB = (int*)(smem + SM_BB);
    {
        long long nn = n0 + tid;
        if (nn >= NNODES) nn = NNODES - 1;
        sBB[tid] = g_batch[nn];
    }
    if (tid < OUTD) ((float*)(smem + SM_BIAS))[tid] = b2[tid];
    copy_B(smem, g_w2hi, g_w2lo, tid);
    __syncthreads();

    {   // gather: x (segs 0-7), agg (8-23), u (24-31)
        const float4* x4 = (const float4*)x;
        const float4* u4 = (const float4*)u;
        const float4* agg4 = (const float4*)g_agg;
        #pragma unroll
        for (int it = 0; it < 32; it++) {
            int idx = tid + it * THREADS;
            int r = idx >> 5, seg = idx & 31;
            long long nn = n0 + r;
            if (nn >= NNODES) nn = NNODES - 1;
            float4 v;
            if (seg < 8)       v = x4[(size_t)nn * 8 + seg];
            else if (seg < 24) v = agg4[(size_t)nn * 16 + (seg - 8)];
            else               v = u4[(size_t)sBB[r] * 8 + (seg - 24)];
            stash4(smem, r, seg * 4, v);
        }
    }
    __syncthreads();

    const int lane = tid & 31, warp = tid >> 5;
    float acc[2][8][4];
    init_acc((const float*)(smem + SM_BIAS), lane, acc);

    gemm_core(sb, warp, lane, acc);

    {   // relu + float4 store
        #pragma unroll
        for (int mt = 0; mt < 2; mt++) {
            long long ra = n0 + warp * 32 + mt * 16 + (lane >> 2);
            long long rb = ra + 8;
            #pragma unroll
            for (int np = 0; np < 4; np++) {
                int c = np * 16 + (lane & 3) * 4;
                if (ra < NNODES)
                    *(float4*)(out + (size_t)ra * OUTD + c) = make_float4(
                        fmaxf(acc[mt][2*np][0], 0.f),   fmaxf(acc[mt][2*np][1], 0.f),
                        fmaxf(acc[mt][2*np+1][0], 0.f), fmaxf(acc[mt][2*np+1][1], 0.f));
                if (rb < NNODES)
                    *(float4*)(out + (size_t)rb * OUTD + c) = make_float4(
                        fmaxf(acc[mt][2*np][2], 0.f),   fmaxf(acc[mt][2*np][3], 0.f),
                        fmaxf(acc[mt][2*np+1][2], 0.f), fmaxf(acc[mt][2*np+1][3], 0.f));
            }
        }
    }
}

// ==================== launcher ====================
extern "C" void kernel_launch(void* const* d_in, const int* in_sizes, int n_in,
                              void* d_out, int out_size) {
    const float* x     = (const float*)d_in[0];
    const void*  ei    = d_in[1];
    const float* ea    = (const float*)d_in[2];
    const float* u     = (const float*)d_in[3];
    const void*  batch = d_in[4];
    const float* W1    = (const float*)d_in[5];
    const float* b1    = (const float*)d_in[6];
    const float* W2    = (const float*)d_in[7];
    const float* b2    = (const float*)d_in[8];
    float* out = (float*)d_out;

    cudaFuncSetAttribute(edge_kernel, cudaFuncAttributeMaxDynamicSharedMemorySize, SM_SZ);
    cudaFuncSetAttribute(node_kernel, cudaFuncAttributeMaxDynamicSharedMemorySize, SM_SZ);

    prep_kernel<<<1480, 256>>>(ei, batch, W1, W2);
    edge_kernel<<<EDGE_BLOCKS, THREADS, SM_SZ>>>(x, ea, u, b1);
    node_kernel<<<NODE_BLOCKS, THREADS, SM_SZ>>>(x, u, b2, out);
}

// round 6
// speedup vs baseline: 2.7747x; 1.5533x over previous
#include <cuda_runtime.h>
#include <cuda_bf16.h>
#include <cstdint>
#include <cstddef>

#define NEDGES  1600000
#define NNODES  100000
#define OUTD    64
#define MTILE   128
#define THREADS 256
#define EDGE_BLOCKS (NEDGES / MTILE)                 // 12500
#define NODE_BLOCKS ((NNODES + MTILE - 1) / MTILE)   // 782

// ---- smem layout (bytes) ----
#define SM_BIAS 0        // 64 floats
#define SM_DST  256      // 128 int
#define SM_SRC  768      // 128 int
#define SM_BB   1280     // 128 int
#define SM_AHI  2048     // 128x128 bf16 (32KB), XOR-swizzled rows of 256B
#define SM_ALO  (SM_AHI + 32768)
#define SM_BHI  (SM_ALO + 32768)   // 64x128 bf16 (16KB) = B^T rows (col-permuted)
#define SM_BLO  (SM_BHI + 16384)
#define SM_SZ   (SM_BLO + 16384)   // 100352

// ---- device scratch ----
__device__ float g_agg[(size_t)NNODES * OUTD];
__device__ int   g_src[NEDGES];
__device__ int   g_dst[NEDGES];
__device__ int   g_batch[NNODES];
__device__ __align__(16) unsigned char g_w1hi[16384];
__device__ __align__(16) unsigned char g_w1lo[16384];
__device__ __align__(16) unsigned char g_w2hi[16384];
__device__ __align__(16) unsigned char g_w2lo[16384];

// ================= helpers =================
__device__ __forceinline__ uint32_t smem_u32(const void* p) {
    uint32_t a;
    asm("{ .reg .u64 t; cvta.to.shared.u64 t, %1; cvt.u32.u64 %0, t; }" : "=r"(a) : "l"(p));
    return a;
}
// split fp32 pair (adjacent K) into packed bf16x2 hi and lo words (low half = even k)
__device__ __forceinline__ void split_pack(float a, float b, uint32_t& hi, uint32_t& lo) {
    uint32_t h;
    asm("cvt.rn.bf16x2.f32 %0, %1, %2;" : "=r"(h) : "f"(b), "f"(a));
    float ha = __uint_as_float(h << 16);
    float hb = __uint_as_float(h & 0xFFFF0000u);
    float la = a - ha, lb = b - hb;
    uint32_t l;
    asm("cvt.rn.bf16x2.f32 %0, %1, %2;" : "=r"(l) : "f"(lb), "f"(la));
    hi = h; lo = l;
}
// swizzled byte offset inside a [row][64-word] tile: word ^= (row&7)<<2
__device__ __forceinline__ uint32_t swz(int r, uint32_t w) {
    return (uint32_t)r * 256u + ((w ^ (uint32_t)((r & 7) << 2)) << 2);
}
__device__ __forceinline__ void stash4(char* smem, int r, int c, float4 v) {
    uint32_t h0, l0, h1, l1;
    split_pack(v.x, v.y, h0, l0);
    split_pack(v.z, v.w, h1, l1);
    uint32_t w0 = (uint32_t)(c >> 1);          // c multiple of 4 -> w0 even
    uint32_t o0 = swz(r, w0), o1 = swz(r, w0 + 1);
    *(uint32_t*)(smem + SM_AHI + o0) = h0;
    *(uint32_t*)(smem + SM_AHI + o1) = h1;
    *(uint32_t*)(smem + SM_ALO + o0) = l0;
    *(uint32_t*)(smem + SM_ALO + o1) = l1;
}
__device__ __forceinline__ void ldsm4(uint32_t addr, uint32_t* r) {
    asm volatile("ldmatrix.sync.aligned.m8n8.x4.shared.b16 {%0,%1,%2,%3}, [%4];"
                 : "=r"(r[0]), "=r"(r[1]), "=r"(r[2]), "=r"(r[3]) : "r"(addr));
}
__device__ __forceinline__ void mma_bf16(float* d, const uint32_t* a, uint32_t b0, uint32_t b1) {
    asm volatile(
        "mma.sync.aligned.m16n8k16.row.col.f32.bf16.bf16.f32 "
        "{%0,%1,%2,%3},{%4,%5,%6,%7},{%8,%9},{%0,%1,%2,%3};"
        : "+f"(d[0]), "+f"(d[1]), "+f"(d[2]), "+f"(d[3])
        : "r"(a[0]), "r"(a[1]), "r"(a[2]), "r"(a[3]), "r"(b0), "r"(b1));
}
__device__ __forceinline__ void red4(float* p, float v0, float v1, float v2, float v3) {
    asm volatile("red.global.add.v4.f32 [%0], {%1,%2,%3,%4};"
                 :: "l"(p), "f"(v0), "f"(v1), "f"(v2), "f"(v3) : "memory");
}

// column permutation: physical B^T row n holds weights of logical output column perm_col(n).
__device__ __host__ __forceinline__ int perm_col(int n) {
    int p = n & 15;
    return (n & ~15) + ((p & 7) >> 1) * 4 + ((p >> 3) << 1) + (p & 1);
}

// ==================== prep ====================
__device__ __forceinline__ bool detect_is64(const long long* e64) {
    bool ok = true;
    #pragma unroll
    for (int i = 0; i < 8; i++)
        ok &= ((unsigned long long)e64[i] < (unsigned long long)NNODES);
    return ok;
}
__device__ __forceinline__ void pack_w(unsigned char* hi, unsigned char* lo,
                                       const float* W, int n, int k) {
    int l = perm_col(n);
    float a = W[(size_t)k * OUTD + l];
    float b = W[(size_t)(k + 1) * OUTD + l];
    uint32_t h, lw;
    split_pack(a, b, h, lw);
    uint32_t off = swz(n, (uint32_t)(k >> 1));
    *(uint32_t*)(hi + off) = h;
    *(uint32_t*)(lo + off) = lw;
}

__global__ void prep_kernel(const void* ei_raw, const void* batch_raw,
                            const float* __restrict__ W1, const float* __restrict__ W2) {
    const bool is64 = detect_is64((const long long*)ei_raw);
    const long long* e64 = (const long long*)ei_raw;
    const int*       e32 = (const int*)ei_raw;
    const long long* b64 = (const long long*)batch_raw;
    const int*       b32 = (const int*)batch_raw;

    const int i0 = blockIdx.x * blockDim.x + threadIdx.x;
    const int stride = gridDim.x * blockDim.x;

    for (int e = i0; e < NEDGES; e += stride) {
        g_src[e] = is64 ? (int)e64[e]          : e32[e];
        g_dst[e] = is64 ? (int)e64[NEDGES + e] : e32[NEDGES + e];
    }
    for (int n = i0; n < NNODES; n += stride)
        g_batch[n] = is64 ? (int)b64[n] : b32[n];

    float4* p = (float4*)g_agg;
    const int nz = NNODES * OUTD / 4;
    float4 z = make_float4(0.f, 0.f, 0.f, 0.f);
    for (int i = i0; i < nz; i += stride) p[i] = z;

    for (int q = i0; q < 4096; q += stride) {   // 64 n x 64 k-pairs
        int n = q >> 6, k = (q & 63) << 1;
        pack_w(g_w1hi, g_w1lo, W1, n, k);
        pack_w(g_w2hi, g_w2lo, W2, n, k);
    }
}

// ==================== shared pieces ====================
__device__ __forceinline__ void copy_B(char* smem, const unsigned char* whi,
                                       const unsigned char* wlo, int tid) {
    const float4* h4 = (const float4*)whi;
    const float4* l4 = (const float4*)wlo;
    float4* dh = (float4*)(smem + SM_BHI);
    float4* dl = (float4*)(smem + SM_BLO);
    #pragma unroll
    for (int i = 0; i < 1024 / THREADS; i++) {
        dh[tid + i * THREADS] = h4[tid + i * THREADS];
        dl[tid + i * THREADS] = l4[tid + i * THREADS];
    }
}

// init accumulators with bias; col layout per perm_col scheme
__device__ __forceinline__ void init_acc(const float* bias, int lane, float acc[8][4]) {
    #pragma unroll
    for (int j = 0; j < 8; j++) {
        int c = (j >> 1) * 16 + (lane & 3) * 4 + (j & 1) * 2;
        float b0 = bias[c], b1 = bias[c + 1];
        acc[j][0] = b0; acc[j][1] = b1; acc[j][2] = b0; acc[j][3] = b1;
    }
}

// 3-pass split GEMM, one 16-row m-tile per warp (warp in 0..7)
__device__ __forceinline__ void gemm_core(uint32_t sb, int warp, int lane,
                                          float acc[8][4]) {
    const int j  = lane >> 3;
    const int rr = lane & 7;
    const uint32_t xo = (uint32_t)(rr << 2);
    const int rowA = warp * 16 + ((j & 1) << 3) + rr;
    const int rowB = ((j & 1) << 3) + rr;               // +16 per n-pair
    const uint32_t ksg = (uint32_t)((j >> 1) << 2);     // word offset 0 or 4

    #pragma unroll
    for (int ks = 0; ks < 8; ks++) {
        const uint32_t byte = (((uint32_t)(ks * 8) + ksg) ^ xo) << 2;
        uint32_t ah[4], al[4];
        const uint32_t aAddr = sb + SM_AHI + (uint32_t)rowA * 256 + byte;
        ldsm4(aAddr,         ah);
        ldsm4(aAddr + 32768, al);
        #pragma unroll
        for (int np = 0; np < 4; np++) {
            uint32_t bh[4], bl[4];
            const uint32_t bAddr = sb + SM_BHI + (uint32_t)(rowB + np * 16) * 256 + byte;
            ldsm4(bAddr,          bh);
            ldsm4(bAddr + 16384,  bl);
            mma_bf16(acc[2*np],   ah, bh[0], bh[2]);
            mma_bf16(acc[2*np],   ah, bl[0], bl[2]);
            mma_bf16(acc[2*np],   al, bh[0], bh[2]);
            mma_bf16(acc[2*np+1], ah, bh[1], bh[3]);
            mma_bf16(acc[2*np+1], ah, bl[1], bl[3]);
            mma_bf16(acc[2*np+1], al, bh[1], bh[3]);
        }
    }
}

// ==================== edge kernel ====================
__global__ void __launch_bounds__(THREADS) edge_kernel(
    const float* __restrict__ x, const float* __restrict__ ea,
    const float* __restrict__ u, const float* __restrict__ b1)
{
    extern __shared__ char smem[];
    const uint32_t sb = smem_u32(smem);
    const int tid = threadIdx.x;
    const long long e0 = (long long)blockIdx.x * MTILE;

    int* sDst = (int*)(smem + SM_DST);
    int* sSrc = (int*)(smem + SM_SRC);
    int* sBB  = (int*)(smem + SM_BB);

    if (tid < MTILE) {   // indices: thread = row
        int e = (int)e0 + tid;
        int s = g_src[e];
        sSrc[tid] = s;
        sDst[tid] = g_dst[e];
        sBB[tid]  = g_batch[s];
    }
    if (tid < OUTD) ((float*)(smem + SM_BIAS))[tid] = b1[tid];
    copy_B(smem, g_w1hi, g_w1lo, tid);
    __syncthreads();

    {   // gather: coalesced (row, seg) decomposition, 16 iters/thread
        const float4* x4  = (const float4*)x;
        const float4* ea4 = (const float4*)ea;
        const float4* u4  = (const float4*)u;
        #pragma unroll
        for (int it = 0; it < 16; it++) {
            int idx = tid + it * THREADS;
            int r = idx >> 5, seg = idx & 31;
            int q = seg >> 3, f = seg & 7;
            float4 v;
            if (q == 0)      v = x4[(size_t)sDst[r] * 8 + f];
            else if (q == 1) v = x4[(size_t)sSrc[r] * 8 + f];
            else if (q == 2) v = ea4[(e0 + r) * 8 + f];
            else             v = u4[(size_t)sBB[r] * 8 + f];
            stash4(smem, r, seg * 4, v);
        }
    }
    __syncthreads();

    const int lane = tid & 31, warp = tid >> 5;
    float acc[8][4];
    init_acc((const float*)(smem + SM_BIAS), lane, acc);

    gemm_core(sb, warp, lane, acc);

    {   // relu + v4 scatter (bias already in acc)
        int ra = warp * 16 + (lane >> 2);
        int rb = ra + 8;
        float* pa = g_agg + (size_t)sDst[ra] * OUTD + (lane & 3) * 4;
        float* pb = g_agg + (size_t)sDst[rb] * OUTD + (lane & 3) * 4;
        #pragma unroll
        for (int np = 0; np < 4; np++) {
            red4(pa + np * 16,
                 fmaxf(acc[2*np][0], 0.f),   fmaxf(acc[2*np][1], 0.f),
                 fmaxf(acc[2*np+1][0], 0.f), fmaxf(acc[2*np+1][1], 0.f));
            red4(pb + np * 16,
                 fmaxf(acc[2*np][2], 0.f),   fmaxf(acc[2*np][3], 0.f),
                 fmaxf(acc[2*np+1][2], 0.f), fmaxf(acc[2*np+1][3], 0.f));
        }
    }
}

// ==================== node kernel ====================
__global__ void __launch_bounds__(THREADS) node_kernel(
    const float* __restrict__ x, const float* __restrict__ u,
    const float* __restrict__ b2, float* __restrict__ out)
{
    extern __shared__ char smem[];
    const uint32_t sb = smem_u32(smem);
    const int tid = threadIdx.x;
    const long long n0 = (long long)blockIdx.x * MTILE;

    int* sBB = (int*)(smem + SM_BB);
    if (tid < MTILE) {
        long long nn = n0 + tid;
        if (nn >= NNODES) nn = NNODES - 1;
        sBB[tid] = g_batch[nn];
    }
    if (tid < OUTD) ((float*)(smem + SM_BIAS))[tid] = b2[tid];
    copy_B(smem, g_w2hi, g_w2lo, tid);
    __syncthreads();

    {   // gather: x (segs 0-7), agg (8-23), u (24-31)
        const float4* x4 = (const float4*)x;
        const float4* u4 = (const float4*)u;
        const float4* agg4 = (const float4*)g_agg;
        #pragma unroll
        for (int it = 0; it < 16; it++) {
            int idx = tid + it * THREADS;
            int r = idx >> 5, seg = idx & 31;
            long long nn = n0 + r;
            if (nn >= NNODES) nn = NNODES - 1;
            float4 v;
            if (seg < 8)       v = x4[(size_t)nn * 8 + seg];
            else if (seg < 24) v = agg4[(size_t)nn * 16 + (seg - 8)];
            else               v = u4[(size_t)sBB[r] * 8 + (seg - 24)];
            stash4(smem, r, seg * 4, v);
        }
    }
    __syncthreads();

    const int lane = tid & 31, warp = tid >> 5;
    float acc[8][4];
    init_acc((const float*)(smem + SM_BIAS), lane, acc);

    gemm_core(sb, warp, lane, acc);

    {   // relu + float4 store
        long long ra = n0 + warp * 16 + (lane >> 2);
        long long rb = ra + 8;
        #pragma unroll
        for (int np = 0; np < 4; np++) {
            int c = np * 16 + (lane & 3) * 4;
            if (ra < NNODES)
                *(float4*)(out + (size_t)ra * OUTD + c) = make_float4(
                    fmaxf(acc[2*np][0], 0.f),   fmaxf(acc[2*np][1], 0.f),
                    fmaxf(acc[2*np+1][0], 0.f), fmaxf(acc[2*np+1][1], 0.f));
            if (rb < NNODES)
                *(float4*)(out + (size_t)rb * OUTD + c) = make_float4(
                    fmaxf(acc[2*np][2], 0.f),   fmaxf(acc[2*np][3], 0.f),
                    fmaxf(acc[2*np+1][2], 0.f), fmaxf(acc[2*np+1][3], 0.f));
        }
    }
}

// ==================== launcher ====================
extern "C" void kernel_launch(void* const* d_in, const int* in_sizes, int n_in,
                              void* d_out, int out_size) {
    const float* x     = (const float*)d_in[0];
    const void*  ei    = d_in[1];
    const float* ea    = (const float*)d_in[2];
    const float* u     = (const float*)d_in[3];
    const void*  batch = d_in[4];
    const float* W1    = (const float*)d_in[5];
    const float* b1    = (const float*)d_in[6];
    const float* W2    = (const float*)d_in[7];
    const float* b2    = (const float*)d_in[8];
    float* out = (float*)d_out;

    cudaFuncSetAttribute(edge_kernel, cudaFuncAttributeMaxDynamicSharedMemorySize, SM_SZ);
    cudaFuncSetAttribute(node_kernel, cudaFuncAttributeMaxDynamicSharedMemorySize, SM_SZ);

    prep_kernel<<<1480, 256>>>(ei, batch, W1, W2);
    edge_kernel<<<EDGE_BLOCKS, THREADS, SM_SZ>>>(x, ea, u, b1);
    node_kernel<<<NODE_BLOCKS, THREADS, SM_SZ>>>(x, u, b2, out);
}

// round 7
// speedup vs baseline: 3.7574x; 1.3541x over previous
#include <cuda_runtime.h>
#include <cuda_bf16.h>
#include <cstdint>
#include <cstddef>

#define NEDGES  1600000
#define NNODES  100000
#define OUTD    64
#define MTILE   128
#define THREADS 512
#define EDGE_BLOCKS (NEDGES / MTILE)                 // 12500
#define NODE_BLOCKS ((NNODES + MTILE - 1) / MTILE)   // 782

// ---- smem layout (bytes) ----
#define SM_BIAS 0        // 64 floats
#define SM_DST  256      // 128 int
#define SM_SRC  768      // 128 int
#define SM_BB   1280     // 128 int
#define SM_AHI  2048     // 128x128 bf16 (32KB), XOR-swizzled rows of 256B
#define SM_ALO  (SM_AHI + 32768)
#define SM_BHI  (SM_ALO + 32768)   // 64x128 bf16 (16KB) = B^T rows (col-permuted)
#define SM_BLO  (SM_BHI + 16384)
#define SM_SZ   (SM_BLO + 16384)   // 100352

// ---- device scratch ----
__device__ float g_agg[(size_t)NNODES * OUTD];
__device__ int   g_src[NEDGES];
__device__ int   g_dst[NEDGES];
__device__ int   g_batch[NNODES];
__device__ __align__(16) unsigned char g_w1hi[16384];
__device__ __align__(16) unsigned char g_w1lo[16384];
__device__ __align__(16) unsigned char g_w2hi[16384];
__device__ __align__(16) unsigned char g_w2lo[16384];

// ================= helpers =================
__device__ __forceinline__ uint32_t smem_u32(const void* p) {
    uint32_t a;
    asm("{ .reg .u64 t; cvta.to.shared.u64 t, %1; cvt.u32.u64 %0, t; }" : "=r"(a) : "l"(p));
    return a;
}
// split fp32 pair (adjacent K) into packed bf16x2 hi and lo words (low half = even k)
__device__ __forceinline__ void split_pack(float a, float b, uint32_t& hi, uint32_t& lo) {
    uint32_t h;
    asm("cvt.rn.bf16x2.f32 %0, %1, %2;" : "=r"(h) : "f"(b), "f"(a));
    float ha = __uint_as_float(h << 16);
    float hb = __uint_as_float(h & 0xFFFF0000u);
    float la = a - ha, lb = b - hb;
    uint32_t l;
    asm("cvt.rn.bf16x2.f32 %0, %1, %2;" : "=r"(l) : "f"(lb), "f"(la));
    hi = h; lo = l;
}
// swizzled byte offset inside a [row][64-word] tile: word ^= (row&7)<<2
__device__ __forceinline__ uint32_t swz(int r, uint32_t w) {
    return (uint32_t)r * 256u + ((w ^ (uint32_t)((r & 7) << 2)) << 2);
}
__device__ __forceinline__ void stash4(char* smem, int r, int c, float4 v) {
    uint32_t h0, l0, h1, l1;
    split_pack(v.x, v.y, h0, l0);
    split_pack(v.z, v.w, h1, l1);
    uint32_t w0 = (uint32_t)(c >> 1);          // c multiple of 4 -> w0 even
    uint32_t o0 = swz(r, w0), o1 = swz(r, w0 + 1);
    *(uint32_t*)(smem + SM_AHI + o0) = h0;
    *(uint32_t*)(smem + SM_AHI + o1) = h1;
    *(uint32_t*)(smem + SM_ALO + o0) = l0;
    *(uint32_t*)(smem + SM_ALO + o1) = l1;
}
__device__ __forceinline__ void ldsm4(uint32_t addr, uint32_t* r) {
    asm volatile("ldmatrix.sync.aligned.m8n8.x4.shared.b16 {%0,%1,%2,%3}, [%4];"
                 : "=r"(r[0]), "=r"(r[1]), "=r"(r[2]), "=r"(r[3]) : "r"(addr));
}
__device__ __forceinline__ void mma_bf16(float* d, const uint32_t* a, uint32_t b0, uint32_t b1) {
    asm volatile(
        "mma.sync.aligned.m16n8k16.row.col.f32.bf16.bf16.f32 "
        "{%0,%1,%2,%3},{%4,%5,%6,%7},{%8,%9},{%0,%1,%2,%3};"
        : "+f"(d[0]), "+f"(d[1]), "+f"(d[2]), "+f"(d[3])
        : "r"(a[0]), "r"(a[1]), "r"(a[2]), "r"(a[3]), "r"(b0), "r"(b1));
}
__device__ __forceinline__ void red4(float* p, float v0, float v1, float v2, float v3) {
    asm volatile("red.global.add.v4.f32 [%0], {%1,%2,%3,%4};"
                 :: "l"(p), "f"(v0), "f"(v1), "f"(v2), "f"(v3) : "memory");
}

// column permutation: physical B^T row n holds weights of logical output column perm_col(n).
__device__ __host__ __forceinline__ int perm_col(int n) {
    int p = n & 15;
    return (n & ~15) + ((p & 7) >> 1) * 4 + ((p >> 3) << 1) + (p & 1);
}

// ==================== prep ====================
__device__ __forceinline__ bool detect_is64(const long long* e64) {
    bool ok = true;
    #pragma unroll
    for (int i = 0; i < 8; i++)
        ok &= ((unsigned long long)e64[i] < (unsigned long long)NNODES);
    return ok;
}
__device__ __forceinline__ void pack_w(unsigned char* hi, unsigned char* lo,
                                       const float* W, int n, int k) {
    int l = perm_col(n);
    float a = W[(size_t)k * OUTD + l];
    float b = W[(size_t)(k + 1) * OUTD + l];
    uint32_t h, lw;
    split_pack(a, b, h, lw);
    uint32_t off = swz(n, (uint32_t)(k >> 1));
    *(uint32_t*)(hi + off) = h;
    *(uint32_t*)(lo + off) = lw;
}

__global__ void prep_kernel(const void* ei_raw, const void* batch_raw,
                            const float* __restrict__ W1, const float* __restrict__ W2) {
    const bool is64 = detect_is64((const long long*)ei_raw);
    const long long* e64 = (const long long*)ei_raw;
    const int*       e32 = (const int*)ei_raw;
    const long long* b64 = (const long long*)batch_raw;
    const int*       b32 = (const int*)batch_raw;

    const int i0 = blockIdx.x * blockDim.x + threadIdx.x;
    const int stride = gridDim.x * blockDim.x;

    for (int e = i0; e < NEDGES; e += stride) {
        g_src[e] = is64 ? (int)e64[e]          : e32[e];
        g_dst[e] = is64 ? (int)e64[NEDGES + e] : e32[NEDGES + e];
    }
    for (int n = i0; n < NNODES; n += stride)
        g_batch[n] = is64 ? (int)b64[n] : b32[n];

    float4* p = (float4*)g_agg;
    const int nz = NNODES * OUTD / 4;
    float4 z = make_float4(0.f, 0.f, 0.f, 0.f);
    for (int i = i0; i < nz; i += stride) p[i] = z;

    for (int q = i0; q < 4096; q += stride) {   // 64 n x 64 k-pairs
        int n = q >> 6, k = (q & 63) << 1;
        pack_w(g_w1hi, g_w1lo, W1, n, k);
        pack_w(g_w2hi, g_w2lo, W2, n, k);
    }
}

// ==================== shared pieces ====================
__device__ __forceinline__ void copy_B(char* smem, const unsigned char* whi,
                                       const unsigned char* wlo, int tid) {
    const float4* h4 = (const float4*)whi;
    const float4* l4 = (const float4*)wlo;
    float4* dh = (float4*)(smem + SM_BHI);
    float4* dl = (float4*)(smem + SM_BLO);
    #pragma unroll
    for (int i = 0; i < 1024 / THREADS; i++) {
        dh[tid + i * THREADS] = h4[tid + i * THREADS];
        dl[tid + i * THREADS] = l4[tid + i * THREADS];
    }
}

// init accumulators with bias; warp owns 16 rows x cols [nh*32, nh*32+32)
__device__ __forceinline__ void init_acc(const float* bias, int nh, int lane, float acc[4][4]) {
    #pragma unroll
    for (int jl = 0; jl < 4; jl++) {
        int np = nh * 2 + (jl >> 1);
        int c = np * 16 + (lane & 3) * 4 + (jl & 1) * 2;
        float b0 = bias[c], b1 = bias[c + 1];
        acc[jl][0] = b0; acc[jl][1] = b1; acc[jl][2] = b0; acc[jl][3] = b1;
    }
}

// 3-pass split GEMM; warp job: m-tile mt (16 rows), n-half nh (2 n-pairs)
__device__ __forceinline__ void gemm_core(uint32_t sb, int mt, int nh, int lane,
                                          float acc[4][4]) {
    const int j  = lane >> 3;
    const int rr = lane & 7;
    const uint32_t xo = (uint32_t)(rr << 2);
    const int rowA = mt * 16 + ((j & 1) << 3) + rr;
    const int rowB = ((j & 1) << 3) + rr;               // +16 per n-pair
    const uint32_t ksg = (uint32_t)((j >> 1) << 2);     // word offset 0 or 4

    #pragma unroll
    for (int ks = 0; ks < 8; ks++) {
        const uint32_t byte = (((uint32_t)(ks * 8) + ksg) ^ xo) << 2;
        uint32_t ah[4], al[4];
        const uint32_t aAddr = sb + SM_AHI + (uint32_t)rowA * 256 + byte;
        ldsm4(aAddr,         ah);
        ldsm4(aAddr + 32768, al);
        #pragma unroll
        for (int p = 0; p < 2; p++) {
            const int np = nh * 2 + p;
            uint32_t bh[4], bl[4];
            const uint32_t bAddr = sb + SM_BHI + (uint32_t)(rowB + np * 16) * 256 + byte;
            ldsm4(bAddr,          bh);
            ldsm4(bAddr + 16384,  bl);
            mma_bf16(acc[2*p],   ah, bh[0], bh[2]);
            mma_bf16(acc[2*p],   ah, bl[0], bl[2]);
            mma_bf16(acc[2*p],   al, bh[0], bh[2]);
            mma_bf16(acc[2*p+1], ah, bh[1], bh[3]);
            mma_bf16(acc[2*p+1], ah, bl[1], bl[3]);
            mma_bf16(acc[2*p+1], al, bh[1], bh[3]);
        }
    }
}

// ==================== edge kernel ====================
__global__ void __launch_bounds__(THREADS, 2) edge_kernel(
    const float* __restrict__ x, const float* __restrict__ ea,
    const float* __restrict__ u, const float* __restrict__ b1)
{
    extern __shared__ char smem[];
    const uint32_t sb = smem_u32(smem);
    const int tid = threadIdx.x;
    const long long e0 = (long long)blockIdx.x * MTILE;

    int* sDst = (int*)(smem + SM_DST);
    int* sSrc = (int*)(smem + SM_SRC);
    int* sBB  = (int*)(smem + SM_BB);

    if (tid < MTILE) {   // indices: thread = row
        int e = (int)e0 + tid;
        int s = g_src[e];
        sSrc[tid] = s;
        sDst[tid] = g_dst[e];
        sBB[tid]  = g_batch[s];
    }
    if (tid < OUTD) ((float*)(smem + SM_BIAS))[tid] = b1[tid];
    copy_B(smem, g_w1hi, g_w1lo, tid);
    __syncthreads();

    {   // gather: coalesced (row, seg) decomposition, 8 iters/thread
        const float4* x4  = (const float4*)x;
        const float4* ea4 = (const float4*)ea;
        const float4* u4  = (const float4*)u;
        #pragma unroll
        for (int it = 0; it < 8; it++) {
            int idx = tid + it * THREADS;
            int r = idx >> 5, seg = idx & 31;
            int q = seg >> 3, f = seg & 7;
            float4 v;
            if (q == 0)      v = x4[(size_t)sDst[r] * 8 + f];
            else if (q == 1) v = x4[(size_t)sSrc[r] * 8 + f];
            else if (q == 2) v = ea4[(e0 + r) * 8 + f];
            else             v = u4[(size_t)sBB[r] * 8 + f];
            stash4(smem, r, seg * 4, v);
        }
    }
    __syncthreads();

    const int lane = tid & 31, warp = tid >> 5;
    const int mt = warp >> 1, nh = warp & 1;
    float acc[4][4];
    init_acc((const float*)(smem + SM_BIAS), nh, lane, acc);

    gemm_core(sb, mt, nh, lane, acc);

    {   // relu + v4 scatter (bias already in acc)
        int ra = mt * 16 + (lane >> 2);
        int rb = ra + 8;
        float* pa = g_agg + (size_t)sDst[ra] * OUTD + (lane & 3) * 4;
        float* pb = g_agg + (size_t)sDst[rb] * OUTD + (lane & 3) * 4;
        #pragma unroll
        for (int p = 0; p < 2; p++) {
            const int np = nh * 2 + p;
            red4(pa + np * 16,
                 fmaxf(acc[2*p][0], 0.f),   fmaxf(acc[2*p][1], 0.f),
                 fmaxf(acc[2*p+1][0], 0.f), fmaxf(acc[2*p+1][1], 0.f));
            red4(pb + np * 16,
                 fmaxf(acc[2*p][2], 0.f),   fmaxf(acc[2*p][3], 0.f),
                 fmaxf(acc[2*p+1][2], 0.f), fmaxf(acc[2*p+1][3], 0.f));
        }
    }
}

// ==================== node kernel ====================
__global__ void __launch_bounds__(THREADS, 2) node_kernel(
    const float* __restrict__ x, const float* __restrict__ u,
    const float* __restrict__ b2, float* __restrict__ out)
{
    extern __shared__ char smem[];
    const uint32_t sb = smem_u32(smem);
    const int tid = threadIdx.x;
    const long long n0 = (long long)blockIdx.x * MTILE;

    int* sBB = (int*)(smem + SM_BB);
    if (tid < MTILE) {
        long long nn = n0 + tid;
        if (nn >= NNODES) nn = NNODES - 1;
        sBB[tid] = g_batch[nn];
    }
    if (tid < OUTD) ((float*)(smem + SM_BIAS))[tid] = b2[tid];
    copy_B(smem, g_w2hi, g_w2lo, tid);
    __syncthreads();

    {   // gather: x (segs 0-7), agg (8-23), u (24-31)
        const float4* x4 = (const float4*)x;
        const float4* u4 = (const float4*)u;
        const float4* agg4 = (const float4*)g_agg;
        #pragma unroll
        for (int it = 0; it < 8; it++) {
            int idx = tid + it * THREADS;
            int r = idx >> 5, seg = idx & 31;
            long long nn = n0 + r;
            if (nn >= NNODES) nn = NNODES - 1;
            float4 v;
            if (seg < 8)       v = x4[(size_t)nn * 8 + seg];
            else if (seg < 24) v = agg4[(size_t)nn * 16 + (seg - 8)];
            else               v = u4[(size_t)sBB[r] * 8 + (seg - 24)];
            stash4(smem, r, seg * 4, v);
        }
    }
    __syncthreads();

    const int lane = tid & 31, warp = tid >> 5;
    const int mt = warp >> 1, nh = warp & 1;
    float acc[4][4];
    init_acc((const float*)(smem + SM_BIAS), nh, lane, acc);

    gemm_core(sb, mt, nh, lane, acc);

    {   // relu + float4 store
        long long ra = n0 + mt * 16 + (lane >> 2);
        long long rb = ra + 8;
        #pragma unroll
        for (int p = 0; p < 2; p++) {
            const int np = nh * 2 + p;
            int c = np * 16 + (lane & 3) * 4;
            if (ra < NNODES)
                *(float4*)(out + (size_t)ra * OUTD + c) = make_float4(
                    fmaxf(acc[2*p][0], 0.f),   fmaxf(acc[2*p][1], 0.f),
                    fmaxf(acc[2*p+1][0], 0.f), fmaxf(acc[2*p+1][1], 0.f));
            if (rb < NNODES)
                *(float4*)(out + (size_t)rb * OUTD + c) = make_float4(
                    fmaxf(acc[2*p][2], 0.f),   fmaxf(acc[2*p][3], 0.f),
                    fmaxf(acc[2*p+1][2], 0.f), fmaxf(acc[2*p+1][3], 0.f));
        }
    }
}

// ==================== launcher ====================
extern "C" void kernel_launch(void* const* d_in, const int* in_sizes, int n_in,
                              void* d_out, int out_size) {
    const float* x     = (const float*)d_in[0];
    const void*  ei    = d_in[1];
    const float* ea    = (const float*)d_in[2];
    const float* u     = (const float*)d_in[3];
    const void*  batch = d_in[4];
    const float* W1    = (const float*)d_in[5];
    const float* b1    = (const float*)d_in[6];
    const float* W2    = (const float*)d_in[7];
    const float* b2    = (const float*)d_in[8];
    float* out = (float*)d_out;

    cudaFuncSetAttribute(edge_kernel, cudaFuncAttributeMaxDynamicSharedMemorySize, SM_SZ);
    cudaFuncSetAttribute(node_kernel, cudaFuncAttributeMaxDynamicSharedMemorySize, SM_SZ);

    prep_kernel<<<1480, 256>>>(ei, batch, W1, W2);
    edge_kernel<<<EDGE_BLOCKS, THREADS, SM_SZ>>>(x, ea, u, b1);
    node_kernel<<<NODE_BLOCKS, THREADS, SM_SZ>>>(x, u, b2, out);
}

// round 8
// speedup vs baseline: 4.6510x; 1.2378x over previous
#include <cuda_runtime.h>
#include <cuda_bf16.h>
#include <cstdint>
#include <cstddef>

#define NEDGES  1600000
#define NNODES  100000
#define OUTD    64
#define MTILE   128
#define THREADS 512
#define TPB     4                                     // tiles per edge block
#define EDGE_BLOCKS (NEDGES / (MTILE * TPB))          // 3125
#define NODE_BLOCKS ((NNODES + MTILE - 1) / MTILE)    // 782

// ---- smem layout (bytes) ----
#define SM_BIAS 0        // 64 floats
#define SM_DST  256      // 128 int
#define SM_SRC  768      // 128 int
#define SM_BB   1280     // 128 int
#define SM_AHI  2048     // 128x128 bf16 (32KB), XOR-swizzled rows of 256B
#define SM_ALO  (SM_AHI + 32768)
#define SM_BHI  (SM_ALO + 32768)   // 64x128 bf16 (16KB) = B^T rows (col-permuted)
#define SM_BLO  (SM_BHI + 16384)
#define SM_SZ   (SM_BLO + 16384)   // 100352

// ---- device scratch ----
__device__ float g_agg[(size_t)NNODES * OUTD];
__device__ int   g_src[NEDGES];
__device__ int   g_dst[NEDGES];
__device__ int   g_batch[NNODES];
__device__ __align__(16) unsigned char g_w1hi[16384];
__device__ __align__(16) unsigned char g_w1lo[16384];
__device__ __align__(16) unsigned char g_w2hi[16384];
__device__ __align__(16) unsigned char g_w2lo[16384];

// ================= helpers =================
__device__ __forceinline__ uint32_t smem_u32(const void* p) {
    uint32_t a;
    asm("{ .reg .u64 t; cvta.to.shared.u64 t, %1; cvt.u32.u64 %0, t; }" : "=r"(a) : "l"(p));
    return a;
}
// split fp32 pair (adjacent K) into packed bf16x2 hi and lo words (low half = even k)
__device__ __forceinline__ void split_pack(float a, float b, uint32_t& hi, uint32_t& lo) {
    uint32_t h;
    asm("cvt.rn.bf16x2.f32 %0, %1, %2;" : "=r"(h) : "f"(b), "f"(a));
    float ha = __uint_as_float(h << 16);
    float hb = __uint_as_float(h & 0xFFFF0000u);
    float la = a - ha, lb = b - hb;
    uint32_t l;
    asm("cvt.rn.bf16x2.f32 %0, %1, %2;" : "=r"(l) : "f"(lb), "f"(la));
    hi = h; lo = l;
}
// swizzled byte offset inside a [row][64-word] tile: word ^= (row&7)<<2
__device__ __forceinline__ uint32_t swz(int r, uint32_t w) {
    return (uint32_t)r * 256u + ((w ^ (uint32_t)((r & 7) << 2)) << 2);
}
__device__ __forceinline__ void stash4(char* smem, int r, int c, float4 v) {
    uint32_t h0, l0, h1, l1;
    split_pack(v.x, v.y, h0, l0);
    split_pack(v.z, v.w, h1, l1);
    uint32_t w0 = (uint32_t)(c >> 1);          // c multiple of 4 -> w0 even
    uint32_t o0 = swz(r, w0), o1 = swz(r, w0 + 1);
    *(uint32_t*)(smem + SM_AHI + o0) = h0;
    *(uint32_t*)(smem + SM_AHI + o1) = h1;
    *(uint32_t*)(smem + SM_ALO + o0) = l0;
    *(uint32_t*)(smem + SM_ALO + o1) = l1;
}
__device__ __forceinline__ void ldsm4(uint32_t addr, uint32_t* r) {
    asm volatile("ldmatrix.sync.aligned.m8n8.x4.shared.b16 {%0,%1,%2,%3}, [%4];"
                 : "=r"(r[0]), "=r"(r[1]), "=r"(r[2]), "=r"(r[3]) : "r"(addr));
}
__device__ __forceinline__ void mma_bf16(float* d, const uint32_t* a, uint32_t b0, uint32_t b1) {
    asm volatile(
        "mma.sync.aligned.m16n8k16.row.col.f32.bf16.bf16.f32 "
        "{%0,%1,%2,%3},{%4,%5,%6,%7},{%8,%9},{%0,%1,%2,%3};"
        : "+f"(d[0]), "+f"(d[1]), "+f"(d[2]), "+f"(d[3])
        : "r"(a[0]), "r"(a[1]), "r"(a[2]), "r"(a[3]), "r"(b0), "r"(b1));
}
__device__ __forceinline__ void red4(float* p, float v0, float v1, float v2, float v3) {
    asm volatile("red.global.add.v4.f32 [%0], {%1,%2,%3,%4};"
                 :: "l"(p), "f"(v0), "f"(v1), "f"(v2), "f"(v3) : "memory");
}

// column permutation: physical B^T row n holds weights of logical output column perm_col(n).
__device__ __host__ __forceinline__ int perm_col(int n) {
    int p = n & 15;
    return (n & ~15) + ((p & 7) >> 1) * 4 + ((p >> 3) << 1) + (p & 1);
}

// ==================== prep ====================
__device__ __forceinline__ bool detect_is64(const long long* e64) {
    bool ok = true;
    #pragma unroll
    for (int i = 0; i < 8; i++)
        ok &= ((unsigned long long)e64[i] < (unsigned long long)NNODES);
    return ok;
}
__device__ __forceinline__ void pack_w(unsigned char* hi, unsigned char* lo,
                                       const float* W, int n, int k) {
    int l = perm_col(n);
    float a = W[(size_t)k * OUTD + l];
    float b = W[(size_t)(k + 1) * OUTD + l];
    uint32_t h, lw;
    split_pack(a, b, h, lw);
    uint32_t off = swz(n, (uint32_t)(k >> 1));
    *(uint32_t*)(hi + off) = h;
    *(uint32_t*)(lo + off) = lw;
}

__global__ void prep_kernel(const void* ei_raw, const void* batch_raw,
                            const float* __restrict__ W1, const float* __restrict__ W2) {
    const bool is64 = detect_is64((const long long*)ei_raw);
    const long long* e64 = (const long long*)ei_raw;
    const int*       e32 = (const int*)ei_raw;
    const long long* b64 = (const long long*)batch_raw;
    const int*       b32 = (const int*)batch_raw;

    const int i0 = blockIdx.x * blockDim.x + threadIdx.x;
    const int stride = gridDim.x * blockDim.x;

    for (int e = i0; e < NEDGES; e += stride) {
        g_src[e] = is64 ? (int)e64[e]          : e32[e];
        g_dst[e] = is64 ? (int)e64[NEDGES + e] : e32[NEDGES + e];
    }
    for (int n = i0; n < NNODES; n += stride)
        g_batch[n] = is64 ? (int)b64[n] : b32[n];

    float4* p = (float4*)g_agg;
    const int nz = NNODES * OUTD / 4;
    float4 z = make_float4(0.f, 0.f, 0.f, 0.f);
    for (int i = i0; i < nz; i += stride) p[i] = z;

    for (int q = i0; q < 4096; q += stride) {   // 64 n x 64 k-pairs
        int n = q >> 6, k = (q & 63) << 1;
        pack_w(g_w1hi, g_w1lo, W1, n, k);
        pack_w(g_w2hi, g_w2lo, W2, n, k);
    }
}

// ==================== shared pieces ====================
__device__ __forceinline__ void copy_B(char* smem, const unsigned char* whi,
                                       const unsigned char* wlo, int tid) {
    const float4* h4 = (const float4*)whi;
    const float4* l4 = (const float4*)wlo;
    float4* dh = (float4*)(smem + SM_BHI);
    float4* dl = (float4*)(smem + SM_BLO);
    #pragma unroll
    for (int i = 0; i < 1024 / THREADS; i++) {
        dh[tid + i * THREADS] = h4[tid + i * THREADS];
        dl[tid + i * THREADS] = l4[tid + i * THREADS];
    }
}

// init accumulators with bias; warp owns 16 rows x cols [nh*32, nh*32+32)
__device__ __forceinline__ void init_acc(const float* bias, int nh, int lane, float acc[4][4]) {
    #pragma unroll
    for (int jl = 0; jl < 4; jl++) {
        int np = nh * 2 + (jl >> 1);
        int c = np * 16 + (lane & 3) * 4 + (jl & 1) * 2;
        float b0 = bias[c], b1 = bias[c + 1];
        acc[jl][0] = b0; acc[jl][1] = b1; acc[jl][2] = b0; acc[jl][3] = b1;
    }
}

// 3-pass split GEMM; warp job: m-tile mt (16 rows), n-half nh (2 n-pairs)
__device__ __forceinline__ void gemm_core(uint32_t sb, int mt, int nh, int lane,
                                          float acc[4][4]) {
    const int j  = lane >> 3;
    const int rr = lane & 7;
    const uint32_t xo = (uint32_t)(rr << 2);
    const int rowA = mt * 16 + ((j & 1) << 3) + rr;
    const int rowB = ((j & 1) << 3) + rr;               // +16 per n-pair
    const uint32_t ksg = (uint32_t)((j >> 1) << 2);     // word offset 0 or 4

    #pragma unroll
    for (int ks = 0; ks < 8; ks++) {
        const uint32_t byte = (((uint32_t)(ks * 8) + ksg) ^ xo) << 2;
        uint32_t ah[4], al[4];
        const uint32_t aAddr = sb + SM_AHI + (uint32_t)rowA * 256 + byte;
        ldsm4(aAddr,         ah);
        ldsm4(aAddr + 32768, al);
        #pragma unroll
        for (int p = 0; p < 2; p++) {
            const int np = nh * 2 + p;
            uint32_t bh[4], bl[4];
            const uint32_t bAddr = sb + SM_BHI + (uint32_t)(rowB + np * 16) * 256 + byte;
            ldsm4(bAddr,          bh);
            ldsm4(bAddr + 16384,  bl);
            mma_bf16(acc[2*p],   ah, bh[0], bh[2]);
            mma_bf16(acc[2*p],   ah, bl[0], bl[2]);
            mma_bf16(acc[2*p],   al, bh[0], bh[2]);
            mma_bf16(acc[2*p+1], ah, bh[1], bh[3]);
            mma_bf16(acc[2*p+1], ah, bl[1], bl[3]);
            mma_bf16(acc[2*p+1], al, bh[1], bh[3]);
        }
    }
}

// ==================== edge kernel (TPB tiles per block) ====================
__global__ void __launch_bounds__(THREADS, 2) edge_kernel(
    const float* __restrict__ x, const float* __restrict__ ea,
    const float* __restrict__ u, const float* __restrict__ b1)
{
    extern __shared__ char smem[];
    const uint32_t sb = smem_u32(smem);
    const int tid = threadIdx.x;
    const int lane = tid & 31, warp = tid >> 5;
    const int mt = warp >> 1, nh = warp & 1;

    int* sDst = (int*)(smem + SM_DST);
    int* sSrc = (int*)(smem + SM_SRC);
    int* sBB  = (int*)(smem + SM_BB);

    if (tid < OUTD) ((float*)(smem + SM_BIAS))[tid] = b1[tid];
    copy_B(smem, g_w1hi, g_w1lo, tid);   // once per block

    // precompute gather decomposition (loop-invariant)
    int gr[8], gseg[8];
    #pragma unroll
    for (int it = 0; it < 8; it++) {
        int idx = tid + it * THREADS;
        gr[it] = idx >> 5; gseg[it] = idx & 31;
    }
    const int ra = mt * 16 + (lane >> 2);   // epilogue rows
    const int rb = ra + 8;

    for (int tt = 0; tt < TPB; tt++) {
        const long long e0 = ((long long)blockIdx.x * TPB + tt) * MTILE;

        if (tid < MTILE) {   // indices: thread = row
            int e = (int)e0 + tid;
            int s = g_src[e];
            sSrc[tid] = s;
            sDst[tid] = g_dst[e];
            sBB[tid]  = g_batch[s];
        }
        __syncthreads();

        // batched gather: 8 independent LDG.128 -> regs (MLP=8), then convert+store
        float4 gv[8];
        {
            const float4* x4  = (const float4*)x;
            const float4* ea4 = (const float4*)ea;
            const float4* u4  = (const float4*)u;
            #pragma unroll
            for (int it = 0; it < 8; it++) {
                int r = gr[it], seg = gseg[it];
                int q = seg >> 3, f = seg & 7;
                const float4* p;
                if (q == 0)      p = x4  + (size_t)sDst[r] * 8 + f;
                else if (q == 1) p = x4  + (size_t)sSrc[r] * 8 + f;
                else if (q == 2) p = ea4 + (size_t)(e0 + r) * 8 + f;
                else             p = u4  + (size_t)sBB[r] * 8 + f;
                gv[it] = *p;
            }
            #pragma unroll
            for (int it = 0; it < 8; it++)
                stash4(smem, gr[it], gseg[it] * 4, gv[it]);
        }
        const int da = sDst[ra], db = sDst[rb];   // to regs before any overwrite
        __syncthreads();

        float acc[4][4];
        init_acc((const float*)(smem + SM_BIAS), nh, lane, acc);
        gemm_core(sb, mt, nh, lane, acc);

        {   // relu + v4 scatter (regs only; bias already in acc)
            float* pa = g_agg + (size_t)da * OUTD + (lane & 3) * 4;
            float* pb = g_agg + (size_t)db * OUTD + (lane & 3) * 4;
            #pragma unroll
            for (int p = 0; p < 2; p++) {
                const int np = nh * 2 + p;
                red4(pa + np * 16,
                     fmaxf(acc[2*p][0], 0.f),   fmaxf(acc[2*p][1], 0.f),
                     fmaxf(acc[2*p+1][0], 0.f), fmaxf(acc[2*p+1][1], 0.f));
                red4(pb + np * 16,
                     fmaxf(acc[2*p][2], 0.f),   fmaxf(acc[2*p][3], 0.f),
                     fmaxf(acc[2*p+1][2], 0.f), fmaxf(acc[2*p+1][3], 0.f));
            }
        }
        __syncthreads();   // all gemm reads of A done before next tile rewrites
    }
}

// ==================== node kernel ====================
__global__ void __launch_bounds__(THREADS, 2) node_kernel(
    const float* __restrict__ x, const float* __restrict__ u,
    const float* __restrict__ b2, float* __restrict__ out)
{
    extern __shared__ char smem[];
    const uint32_t sb = smem_u32(smem);
    const int tid = threadIdx.x;
    const long long n0 = (long long)blockIdx.x * MTILE;

    int* sBB = (int*)(smem + SM_BB);
    if (tid < MTILE) {
        long long nn = n0 + tid;
        if (nn >= NNODES) nn = NNODES - 1;
        sBB[tid] = g_batch[nn];
    }
    if (tid < OUTD) ((float*)(smem + SM_BIAS))[tid] = b2[tid];
    copy_B(smem, g_w2hi, g_w2lo, tid);
    __syncthreads();

    {   // batched gather: x (segs 0-7), agg (8-23), u (24-31)
        const float4* x4 = (const float4*)x;
        const float4* u4 = (const float4*)u;
        const float4* agg4 = (const float4*)g_agg;
        float4 gv[8];
        int gr[8], gseg[8];
        #pragma unroll
        for (int it = 0; it < 8; it++) {
            int idx = tid + it * THREADS;
            int r = idx >> 5, seg = idx & 31;
            gr[it] = r; gseg[it] = seg;
            long long nn = n0 + r;
            if (nn >= NNODES) nn = NNODES - 1;
            const float4* p;
            if (seg < 8)       p = x4   + (size_t)nn * 8 + seg;
            else if (seg < 24) p = agg4 + (size_t)nn * 16 + (seg - 8);
            else               p = u4   + (size_t)sBB[r] * 8 + (seg - 24);
            gv[it] = *p;
        }
        #pragma unroll
        for (int it = 0; it < 8; it++)
            stash4(smem, gr[it], gseg[it] * 4, gv[it]);
    }
    __syncthreads();

    const int lane = tid & 31, warp = tid >> 5;
    const int mt = warp >> 1, nh = warp & 1;
    float acc[4][4];
    init_acc((const float*)(smem + SM_BIAS), nh, lane, acc);

    gemm_core(sb, mt, nh, lane, acc);

    {   // relu + float4 store
        long long ra = n0 + mt * 16 + (lane >> 2);
        long long rb = ra + 8;
        #pragma unroll
        for (int p = 0; p < 2; p++) {
            const int np = nh * 2 + p;
            int c = np * 16 + (lane & 3) * 4;
            if (ra < NNODES)
                *(float4*)(out + (size_t)ra * OUTD + c) = make_float4(
                    fmaxf(acc[2*p][0], 0.f),   fmaxf(acc[2*p][1], 0.f),
                    fmaxf(acc[2*p+1][0], 0.f), fmaxf(acc[2*p+1][1], 0.f));
            if (rb < NNODES)
                *(float4*)(out + (size_t)rb * OUTD + c) = make_float4(
                    fmaxf(acc[2*p][2], 0.f),   fmaxf(acc[2*p][3], 0.f),
                    fmaxf(acc[2*p+1][2], 0.f), fmaxf(acc[2*p+1][3], 0.f));
        }
    }
}

// ==================== launcher ====================
extern "C" void kernel_launch(void* const* d_in, const int* in_sizes, int n_in,
                              void* d_out, int out_size) {
    const float* x     = (const float*)d_in[0];
    const void*  ei    = d_in[1];
    const float* ea    = (const float*)d_in[2];
    const float* u     = (const float*)d_in[3];
    const void*  batch = d_in[4];
    const float* W1    = (const float*)d_in[5];
    const float* b1    = (const float*)d_in[6];
    const float* W2    = (const float*)d_in[7];
    const float* b2    = (const float*)d_in[8];
    float* out = (float*)d_out;

    cudaFuncSetAttribute(edge_kernel, cudaFuncAttributeMaxDynamicSharedMemorySize, SM_SZ);
    cudaFuncSetAttribute(node_kernel, cudaFuncAttributeMaxDynamicSharedMemorySize, SM_SZ);

    prep_kernel<<<1480, 256>>>(ei, batch, W1, W2);
    edge_kernel<<<EDGE_BLOCKS, THREADS, SM_SZ>>>(x, ea, u, b1);
    node_kernel<<<NODE_BLOCKS, THREADS, SM_SZ>>>(x, u, b2, out);
}

// round 9
// speedup vs baseline: 6.3843x; 1.3727x over previous
#include <cuda_runtime.h>
#include <cuda_bf16.h>
#include <cstdint>
#include <cstddef>

#define NEDGES  1600000
#define NNODES  100000
#define OUTD    64
#define MTILE   128
#define THREADS 512
#define TPB     4                                     // tiles per edge block
#define EDGE_BLOCKS (NEDGES / (MTILE * TPB))          // 3125
#define NODE_BLOCKS ((NNODES + MTILE - 1) / MTILE)    // 782

// ---- edge kernel smem layout (fp16 single-pass) ----
#define E_BIAS 0         // 64 floats
#define E_DST  256
#define E_SRC  768
#define E_BB   1280
#define E_A    2048      // 128x128 fp16 (32KB), swizzled 256B rows
#define E_B    (E_A + 32768)   // 64x128 fp16 (16KB)
#define E_SZ   (E_B + 16384)   // 51200

// ---- node kernel smem layout (bf16 3-pass) ----
#define SM_BIAS 0
#define SM_BB   1280
#define SM_AHI  2048
#define SM_ALO  (SM_AHI + 32768)
#define SM_BHI  (SM_ALO + 32768)
#define SM_BLO  (SM_BHI + 16384)
#define SM_SZ   (SM_BLO + 16384)   // 100352

// ---- device scratch ----
__device__ float g_agg[(size_t)NNODES * OUTD];
__device__ int   g_src[NEDGES];
__device__ int   g_dst[NEDGES];
__device__ int   g_batch[NNODES];
__device__ __align__(16) unsigned char g_w1f16[16384];   // W1 fp16, B^T swizzled
__device__ __align__(16) unsigned char g_w2hi[16384];
__device__ __align__(16) unsigned char g_w2lo[16384];

// ================= helpers =================
__device__ __forceinline__ uint32_t smem_u32(const void* p) {
    uint32_t a;
    asm("{ .reg .u64 t; cvta.to.shared.u64 t, %1; cvt.u32.u64 %0, t; }" : "=r"(a) : "l"(p));
    return a;
}
// pack fp32 pair (adjacent K) into one f16x2 word (low half = even k)
__device__ __forceinline__ uint32_t pack_f16(float a, float b) {
    uint32_t w;
    asm("cvt.rn.f16x2.f32 %0, %1, %2;" : "=r"(w) : "f"(b), "f"(a));
    return w;
}
// split fp32 pair into packed bf16x2 hi and lo words (low half = even k)
__device__ __forceinline__ void split_pack(float a, float b, uint32_t& hi, uint32_t& lo) {
    uint32_t h;
    asm("cvt.rn.bf16x2.f32 %0, %1, %2;" : "=r"(h) : "f"(b), "f"(a));
    float ha = __uint_as_float(h << 16);
    float hb = __uint_as_float(h & 0xFFFF0000u);
    float la = a - ha, lb = b - hb;
    uint32_t l;
    asm("cvt.rn.bf16x2.f32 %0, %1, %2;" : "=r"(l) : "f"(lb), "f"(la));
    hi = h; lo = l;
}
// swizzled byte offset inside a [row][64-word] tile: word ^= (row&7)<<2
__device__ __forceinline__ uint32_t swz(int r, uint32_t w) {
    return (uint32_t)r * 256u + ((w ^ (uint32_t)((r & 7) << 2)) << 2);
}
// fp16 stash (edge)
__device__ __forceinline__ void stash4_f16(char* smem, int r, int c, float4 v) {
    uint32_t w0v = pack_f16(v.x, v.y);
    uint32_t w1v = pack_f16(v.z, v.w);
    uint32_t w0 = (uint32_t)(c >> 1);
    *(uint32_t*)(smem + E_A + swz(r, w0))     = w0v;
    *(uint32_t*)(smem + E_A + swz(r, w0 + 1)) = w1v;
}
// bf16 split stash (node)
__device__ __forceinline__ void stash4_bf(char* smem, int r, int c, float4 v) {
    uint32_t h0, l0, h1, l1;
    split_pack(v.x, v.y, h0, l0);
    split_pack(v.z, v.w, h1, l1);
    uint32_t w0 = (uint32_t)(c >> 1);
    uint32_t o0 = swz(r, w0), o1 = swz(r, w0 + 1);
    *(uint32_t*)(smem + SM_AHI + o0) = h0;
    *(uint32_t*)(smem + SM_AHI + o1) = h1;
    *(uint32_t*)(smem + SM_ALO + o0) = l0;
    *(uint32_t*)(smem + SM_ALO + o1) = l1;
}
__device__ __forceinline__ void ldsm4(uint32_t addr, uint32_t* r) {
    asm volatile("ldmatrix.sync.aligned.m8n8.x4.shared.b16 {%0,%1,%2,%3}, [%4];"
                 : "=r"(r[0]), "=r"(r[1]), "=r"(r[2]), "=r"(r[3]) : "r"(addr));
}
__device__ __forceinline__ void mma_bf16(float* d, const uint32_t* a, uint32_t b0, uint32_t b1) {
    asm volatile(
        "mma.sync.aligned.m16n8k16.row.col.f32.bf16.bf16.f32 "
        "{%0,%1,%2,%3},{%4,%5,%6,%7},{%8,%9},{%0,%1,%2,%3};"
        : "+f"(d[0]), "+f"(d[1]), "+f"(d[2]), "+f"(d[3])
        : "r"(a[0]), "r"(a[1]), "r"(a[2]), "r"(a[3]), "r"(b0), "r"(b1));
}
__device__ __forceinline__ void mma_f16(float* d, const uint32_t* a, uint32_t b0, uint32_t b1) {
    asm volatile(
        "mma.sync.aligned.m16n8k16.row.col.f32.f16.f16.f32 "
        "{%0,%1,%2,%3},{%4,%5,%6,%7},{%8,%9},{%0,%1,%2,%3};"
        : "+f"(d[0]), "+f"(d[1]), "+f"(d[2]), "+f"(d[3])
        : "r"(a[0]), "r"(a[1]), "r"(a[2]), "r"(a[3]), "r"(b0), "r"(b1));
}
__device__ __forceinline__ void red4(float* p, float v0, float v1, float v2, float v3) {
    asm volatile("red.global.add.v4.f32 [%0], {%1,%2,%3,%4};"
                 :: "l"(p), "f"(v0), "f"(v1), "f"(v2), "f"(v3) : "memory");
}

// column permutation: physical B^T row n holds weights of logical output column perm_col(n).
__device__ __host__ __forceinline__ int perm_col(int n) {
    int p = n & 15;
    return (n & ~15) + ((p & 7) >> 1) * 4 + ((p >> 3) << 1) + (p & 1);
}

// ==================== prep ====================
__device__ __forceinline__ bool detect_is64(const long long* e64) {
    bool ok = true;
    #pragma unroll
    for (int i = 0; i < 8; i++)
        ok &= ((unsigned long long)e64[i] < (unsigned long long)NNODES);
    return ok;
}

__global__ void prep_kernel(const void* ei_raw, const void* batch_raw,
                            const float* __restrict__ W1, const float* __restrict__ W2) {
    const bool is64 = detect_is64((const long long*)ei_raw);
    const long long* e64 = (const long long*)ei_raw;
    const int*       e32 = (const int*)ei_raw;
    const long long* b64 = (const long long*)batch_raw;
    const int*       b32 = (const int*)batch_raw;

    const int i0 = blockIdx.x * blockDim.x + threadIdx.x;
    const int stride = gridDim.x * blockDim.x;

    for (int e = i0; e < NEDGES; e += stride) {
        g_src[e] = is64 ? (int)e64[e]          : e32[e];
        g_dst[e] = is64 ? (int)e64[NEDGES + e] : e32[NEDGES + e];
    }
    for (int n = i0; n < NNODES; n += stride)
        g_batch[n] = is64 ? (int)b64[n] : b32[n];

    float4* p = (float4*)g_agg;
    const int nz = NNODES * OUTD / 4;
    float4 z = make_float4(0.f, 0.f, 0.f, 0.f);
    for (int i = i0; i < nz; i += stride) p[i] = z;

    for (int q = i0; q < 4096; q += stride) {   // 64 n x 64 k-pairs
        int n = q >> 6, k = (q & 63) << 1;
        int l = perm_col(n);
        uint32_t off = swz(n, (uint32_t)(k >> 1));
        // W1 -> fp16 single
        {
            float a = W1[(size_t)k * OUTD + l];
            float b = W1[(size_t)(k + 1) * OUTD + l];
            *(uint32_t*)(g_w1f16 + off) = pack_f16(a, b);
        }
        // W2 -> bf16 hi/lo
        {
            float a = W2[(size_t)k * OUTD + l];
            float b = W2[(size_t)(k + 1) * OUTD + l];
            uint32_t h, lw;
            split_pack(a, b, h, lw);
            *(uint32_t*)(g_w2hi + off) = h;
            *(uint32_t*)(g_w2lo + off) = lw;
        }
    }
}

// ==================== shared pieces ====================
// init accumulators with bias; warp owns 16 rows x cols [nh*32, nh*32+32)
__device__ __forceinline__ void init_acc(const float* bias, int nh, int lane, float acc[4][4]) {
    #pragma unroll
    for (int jl = 0; jl < 4; jl++) {
        int np = nh * 2 + (jl >> 1);
        int c = np * 16 + (lane & 3) * 4 + (jl & 1) * 2;
        float b0 = bias[c], b1 = bias[c + 1];
        acc[jl][0] = b0; acc[jl][1] = b1; acc[jl][2] = b0; acc[jl][3] = b1;
    }
}

// 1-pass fp16 GEMM (edge)
__device__ __forceinline__ void gemm_f16(uint32_t sb, int mt, int nh, int lane,
                                         float acc[4][4]) {
    const int j  = lane >> 3;
    const int rr = lane & 7;
    const uint32_t xo = (uint32_t)(rr << 2);
    const int rowA = mt * 16 + ((j & 1) << 3) + rr;
    const int rowB = ((j & 1) << 3) + rr;
    const uint32_t ksg = (uint32_t)((j >> 1) << 2);

    #pragma unroll
    for (int ks = 0; ks < 8; ks++) {
        const uint32_t byte = (((uint32_t)(ks * 8) + ksg) ^ xo) << 2;
        uint32_t a[4];
        ldsm4(sb + E_A + (uint32_t)rowA * 256 + byte, a);
        #pragma unroll
        for (int p = 0; p < 2; p++) {
            const int np = nh * 2 + p;
            uint32_t b[4];
            ldsm4(sb + E_B + (uint32_t)(rowB + np * 16) * 256 + byte, b);
            mma_f16(acc[2*p],   a, b[0], b[2]);
            mma_f16(acc[2*p+1], a, b[1], b[3]);
        }
    }
}

// 3-pass bf16 split GEMM (node)
__device__ __forceinline__ void gemm_bf16(uint32_t sb, int mt, int nh, int lane,
                                          float acc[4][4]) {
    const int j  = lane >> 3;
    const int rr = lane & 7;
    const uint32_t xo = (uint32_t)(rr << 2);
    const int rowA = mt * 16 + ((j & 1) << 3) + rr;
    const int rowB = ((j & 1) << 3) + rr;
    const uint32_t ksg = (uint32_t)((j >> 1) << 2);

    #pragma unroll
    for (int ks = 0; ks < 8; ks++) {
        const uint32_t byte = (((uint32_t)(ks * 8) + ksg) ^ xo) << 2;
        uint32_t ah[4], al[4];
        const uint32_t aAddr = sb + SM_AHI + (uint32_t)rowA * 256 + byte;
        ldsm4(aAddr,         ah);
        ldsm4(aAddr + 32768, al);
        #pragma unroll
        for (int p = 0; p < 2; p++) {
            const int np = nh * 2 + p;
            uint32_t bh[4], bl[4];
            const uint32_t bAddr = sb + SM_BHI + (uint32_t)(rowB + np * 16) * 256 + byte;
            ldsm4(bAddr,          bh);
            ldsm4(bAddr + 16384,  bl);
            mma_bf16(acc[2*p],   ah, bh[0], bh[2]);
            mma_bf16(acc[2*p],   ah, bl[0], bl[2]);
            mma_bf16(acc[2*p],   al, bh[0], bh[2]);
            mma_bf16(acc[2*p+1], ah, bh[1], bh[3]);
            mma_bf16(acc[2*p+1], ah, bl[1], bl[3]);
            mma_bf16(acc[2*p+1], al, bh[1], bh[3]);
        }
    }
}

// ==================== edge kernel (fp16, TPB tiles per block) ====================
__global__ void __launch_bounds__(THREADS, 2) edge_kernel(
    const float* __restrict__ x, const float* __restrict__ ea,
    const float* __restrict__ u, const float* __restrict__ b1)
{
    extern __shared__ char smem[];
    const uint32_t sb = smem_u32(smem);
    const int tid = threadIdx.x;
    const int lane = tid & 31, warp = tid >> 5;
    const int mt = warp >> 1, nh = warp & 1;

    int* sDst = (int*)(smem + E_DST);
    int* sSrc = (int*)(smem + E_SRC);
    int* sBB  = (int*)(smem + E_BB);

    if (tid < OUTD) ((float*)(smem + E_BIAS))[tid] = b1[tid];
    {   // copy W1 fp16 (16KB) once per block
        const float4* w4 = (const float4*)g_w1f16;
        float4* d4 = (float4*)(smem + E_B);
        #pragma unroll
        for (int i = 0; i < 1024 / THREADS; i++)
            d4[tid + i * THREADS] = w4[tid + i * THREADS];
    }

    int gr[8], gseg[8];
    #pragma unroll
    for (int it = 0; it < 8; it++) {
        int idx = tid + it * THREADS;
        gr[it] = idx >> 5; gseg[it] = idx & 31;
    }
    const int ra = mt * 16 + (lane >> 2);
    const int rb = ra + 8;

    for (int tt = 0; tt < TPB; tt++) {
        const long long e0 = ((long long)blockIdx.x * TPB + tt) * MTILE;

        if (tid < MTILE) {
            int e = (int)e0 + tid;
            int s = g_src[e];
            sSrc[tid] = s;
            sDst[tid] = g_dst[e];
            sBB[tid]  = g_batch[s];
        }
        __syncthreads();

        float4 gv[8];
        {
            const float4* x4  = (const float4*)x;
            const float4* ea4 = (const float4*)ea;
            const float4* u4  = (const float4*)u;
            #pragma unroll
            for (int it = 0; it < 8; it++) {
                int r = gr[it], seg = gseg[it];
                int q = seg >> 3, f = seg & 7;
                const float4* p;
                if (q == 0)      p = x4  + (size_t)sDst[r] * 8 + f;
                else if (q == 1) p = x4  + (size_t)sSrc[r] * 8 + f;
                else if (q == 2) p = ea4 + (size_t)(e0 + r) * 8 + f;
                else             p = u4  + (size_t)sBB[r] * 8 + f;
                gv[it] = *p;
            }
            #pragma unroll
            for (int it = 0; it < 8; it++)
                stash4_f16(smem, gr[it], gseg[it] * 4, gv[it]);
        }
        const int da = sDst[ra], db = sDst[rb];
        __syncthreads();

        float acc[4][4];
        init_acc((const float*)(smem + E_BIAS), nh, lane, acc);
        gemm_f16(sb, mt, nh, lane, acc);

        {
            float* pa = g_agg + (size_t)da * OUTD + (lane & 3) * 4;
            float* pb = g_agg + (size_t)db * OUTD + (lane & 3) * 4;
            #pragma unroll
            for (int p = 0; p < 2; p++) {
                const int np = nh * 2 + p;
                red4(pa + np * 16,
                     fmaxf(acc[2*p][0], 0.f),   fmaxf(acc[2*p][1], 0.f),
                     fmaxf(acc[2*p+1][0], 0.f), fmaxf(acc[2*p+1][1], 0.f));
                red4(pb + np * 16,
                     fmaxf(acc[2*p][2], 0.f),   fmaxf(acc[2*p][3], 0.f),
                     fmaxf(acc[2*p+1][2], 0.f), fmaxf(acc[2*p+1][3], 0.f));
            }
        }
        __syncthreads();
    }
}

// ==================== node kernel (bf16 3-pass) ====================
__global__ void __launch_bounds__(THREADS, 2) node_kernel(
    const float* __restrict__ x, const float* __restrict__ u,
    const float* __restrict__ b2, float* __restrict__ out)
{
    extern __shared__ char smem[];
    const uint32_t sb = smem_u32(smem);
    const int tid = threadIdx.x;
    const long long n0 = (long long)blockIdx.x * MTILE;

    int* sBB = (int*)(smem + SM_BB);
    if (tid < MTILE) {
        long long nn = n0 + tid;
        if (nn >= NNODES) nn = NNODES - 1;
        sBB[tid] = g_batch[nn];
    }
    if (tid < OUTD) ((float*)(smem + SM_BIAS))[tid] = b2[tid];
    {   // copy W2 hi/lo
        const float4* h4 = (const float4*)g_w2hi;
        const float4* l4 = (const float4*)g_w2lo;
        float4* dh = (float4*)(smem + SM_BHI);
        float4* dl = (float4*)(smem + SM_BLO);
        #pragma unroll
        for (int i = 0; i < 1024 / THREADS; i++) {
            dh[tid + i * THREADS] = h4[tid + i * THREADS];
            dl[tid + i * THREADS] = l4[tid + i * THREADS];
        }
    }
    __syncthreads();

    {   // batched gather: x (segs 0-7), agg (8-23), u (24-31)
        const float4* x4 = (const float4*)x;
        const float4* u4 = (const float4*)u;
        const float4* agg4 = (const float4*)g_agg;
        float4 gv[8];
        int gr[8], gseg[8];
        #pragma unroll
        for (int it = 0; it < 8; it++) {
            int idx = tid + it * THREADS;
            int r = idx >> 5, seg = idx & 31;
            gr[it] = r; gseg[it] = seg;
            long long nn = n0 + r;
            if (nn >= NNODES) nn = NNODES - 1;
            const float4* p;
            if (seg < 8)       p = x4   + (size_t)nn * 8 + seg;
            else if (seg < 24) p = agg4 + (size_t)nn * 16 + (seg - 8);
            else               p = u4   + (size_t)sBB[r] * 8 + (seg - 24);
            gv[it] = *p;
        }
        #pragma unroll
        for (int it = 0; it < 8; it++)
            stash4_bf(smem, gr[it], gseg[it] * 4, gv[it]);
    }
    __syncthreads();

    const int lane = tid & 31, warp = tid >> 5;
    const int mt = warp >> 1, nh = warp & 1;
    float acc[4][4];
    init_acc((const float*)(smem + SM_BIAS), nh, lane, acc);

    gemm_bf16(sb, mt, nh, lane, acc);

    {   // relu + float4 store
        long long ra = n0 + mt * 16 + (lane >> 2);
        long long rb = ra + 8;
        #pragma unroll
        for (int p = 0; p < 2; p++) {
            const int np = nh * 2 + p;
            int c = np * 16 + (lane & 3) * 4;
            if (ra < NNODES)
                *(float4*)(out + (size_t)ra * OUTD + c) = make_float4(
                    fmaxf(acc[2*p][0], 0.f),   fmaxf(acc[2*p][1], 0.f),
                    fmaxf(acc[2*p+1][0], 0.f), fmaxf(acc[2*p+1][1], 0.f));
            if (rb < NNODES)
                *(float4*)(out + (size_t)rb * OUTD + c) = make_float4(
                    fmaxf(acc[2*p][2], 0.f),   fmaxf(acc[2*p][3], 0.f),
                    fmaxf(acc[2*p+1][2], 0.f), fmaxf(acc[2*p+1][3], 0.f));
        }
    }
}

// ==================== launcher ====================
extern "C" void kernel_launch(void* const* d_in, const int* in_sizes, int n_in,
                              void* d_out, int out_size) {
    const float* x     = (const float*)d_in[0];
    const void*  ei    = d_in[1];
    const float* ea    = (const float*)d_in[2];
    const float* u     = (const float*)d_in[3];
    const void*  batch = d_in[4];
    const float* W1    = (const float*)d_in[5];
    const float* b1    = (const float*)d_in[6];
    const float* W2    = (const float*)d_in[7];
    const float* b2    = (const float*)d_in[8];
    float* out = (float*)d_out;

    cudaFuncSetAttribute(edge_kernel, cudaFuncAttributeMaxDynamicSharedMemorySize, E_SZ);
    cudaFuncSetAttribute(node_kernel, cudaFuncAttributeMaxDynamicSharedMemorySize, SM_SZ);

    prep_kernel<<<1480, 256>>>(ei, batch, W1, W2);
    edge_kernel<<<EDGE_BLOCKS, THREADS, E_SZ>>>(x, ea, u, b1);
    node_kernel<<<NODE_BLOCKS, THREADS, SM_SZ>>>(x, u, b2, out);
}

// round 11
// speedup vs baseline: 6.9098x; 1.0823x over previous
#include <cuda_runtime.h>
#include <cuda_bf16.h>
#include <cstdint>
#include <cstddef>

#define NEDGES  1600000
#define NNODES  100000
#define OUTD    64
#define MTILE   128
#define THREADS 512
#define TPB     4                                     // tiles per edge block
#define EDGE_BLOCKS (NEDGES / (MTILE * TPB))          // 3125
#define NODE_BLOCKS ((NNODES + MTILE - 1) / MTILE)    // 782

// ---- edge kernel smem layout (fp16, double-buffered A) ----
#define E_BIAS 0         // 64 floats
#define E_DST  256       // 512 ints
#define E_SRC  2304
#define E_BB   4352
#define E_A0   7168      // 128x128 fp16 (32KB), swizzled 256B rows
#define E_A1   (E_A0 + 32768)
#define E_B    (E_A1 + 32768)   // 64x128 fp16 (16KB)
#define E_SZ   (E_B + 16384)    // 89088

// ---- node kernel smem layout (fp16 single buffer) ----
#define N_BIAS 0
#define N_BB   256       // 128 ints
#define N_A    2048      // 32KB
#define N_B    (N_A + 32768)
#define N_SZ   (N_B + 16384)    // 51200

// ---- device scratch ----
__device__ float g_agg[(size_t)NNODES * OUTD];
__device__ int   g_src[NEDGES];
__device__ int   g_dst[NEDGES];
__device__ int   g_batch[NNODES];
__device__ __align__(16) unsigned char g_w1f16[16384];   // W1 fp16, B^T swizzled
__device__ __align__(16) unsigned char g_w2f16[16384];   // W2 fp16, B^T swizzled

// ================= helpers =================
__device__ __forceinline__ uint32_t smem_u32(const void* p) {
    uint32_t a;
    asm("{ .reg .u64 t; cvta.to.shared.u64 t, %1; cvt.u32.u64 %0, t; }" : "=r"(a) : "l"(p));
    return a;
}
__device__ __forceinline__ uint32_t pack_f16(float a, float b) {
    uint32_t w;
    asm("cvt.rn.f16x2.f32 %0, %1, %2;" : "=r"(w) : "f"(b), "f"(a));
    return w;
}
// swizzled byte offset inside a [row][64-word] tile: word ^= (row&7)<<2
__device__ __forceinline__ uint32_t swz(int r, uint32_t w) {
    return (uint32_t)r * 256u + ((w ^ (uint32_t)((r & 7) << 2)) << 2);
}
__device__ __forceinline__ void ldsm4(uint32_t addr, uint32_t* r) {
    asm volatile("ldmatrix.sync.aligned.m8n8.x4.shared.b16 {%0,%1,%2,%3}, [%4];"
                 : "=r"(r[0]), "=r"(r[1]), "=r"(r[2]), "=r"(r[3]) : "r"(addr));
}
__device__ __forceinline__ void mma_f16(float* d, const uint32_t* a, uint32_t b0, uint32_t b1) {
    asm volatile(
        "mma.sync.aligned.m16n8k16.row.col.f32.f16.f16.f32 "
        "{%0,%1,%2,%3},{%4,%5,%6,%7},{%8,%9},{%0,%1,%2,%3};"
        : "+f"(d[0]), "+f"(d[1]), "+f"(d[2]), "+f"(d[3])
        : "r"(a[0]), "r"(a[1]), "r"(a[2]), "r"(a[3]), "r"(b0), "r"(b1));
}
__device__ __forceinline__ void red4(float* p, float v0, float v1, float v2, float v3) {
    asm volatile("red.global.add.v4.f32 [%0], {%1,%2,%3,%4};"
                 :: "l"(p), "f"(v0), "f"(v1), "f"(v2), "f"(v3) : "memory");
}
// column permutation: physical B^T row n holds weights of logical output column perm_col(n).
__device__ __host__ __forceinline__ int perm_col(int n) {
    int p = n & 15;
    return (n & ~15) + ((p & 7) >> 1) * 4 + ((p >> 3) << 1) + (p & 1);
}

// ==================== prep ====================
__device__ __forceinline__ bool detect_is64(const long long* e64) {
    bool ok = true;
    #pragma unroll
    for (int i = 0; i < 8; i++)
        ok &= ((unsigned long long)e64[i] < (unsigned long long)NNODES);
    return ok;
}

__global__ void prep_kernel(const void* ei_raw, const void* batch_raw,
                            const float* __restrict__ W1, const float* __restrict__ W2) {
    const bool is64 = detect_is64((const long long*)ei_raw);
    const long long* e64 = (const long long*)ei_raw;
    const int*       e32 = (const int*)ei_raw;
    const long long* b64 = (const long long*)batch_raw;
    const int*       b32 = (const int*)batch_raw;

    const int i0 = blockIdx.x * blockDim.x + threadIdx.x;
    const int stride = gridDim.x * blockDim.x;

    for (int e = i0; e < NEDGES; e += stride) {
        g_src[e] = is64 ? (int)e64[e]          : e32[e];
        g_dst[e] = is64 ? (int)e64[NEDGES + e] : e32[NEDGES + e];
    }
    for (int n = i0; n < NNODES; n += stride)
        g_batch[n] = is64 ? (int)b64[n] : b32[n];

    float4* p = (float4*)g_agg;
    const int nz = NNODES * OUTD / 4;
    float4 z = make_float4(0.f, 0.f, 0.f, 0.f);
    for (int i = i0; i < nz; i += stride) p[i] = z;

    for (int q = i0; q < 4096; q += stride) {   // 64 n x 64 k-pairs
        int n = q >> 6, k = (q & 63) << 1;
        int l = perm_col(n);
        uint32_t off = swz(n, (uint32_t)(k >> 1));
        *(uint32_t*)(g_w1f16 + off) =
            pack_f16(W1[(size_t)k * OUTD + l], W1[(size_t)(k + 1) * OUTD + l]);
        *(uint32_t*)(g_w2f16 + off) =
            pack_f16(W2[(size_t)k * OUTD + l], W2[(size_t)(k + 1) * OUTD + l]);
    }
}

// ==================== shared pieces ====================
__device__ __forceinline__ void init_acc(const float* bias, int nh, int lane, float acc[4][4]) {
    #pragma unroll
    for (int jl = 0; jl < 4; jl++) {
        int np = nh * 2 + (jl >> 1);
        int c = np * 16 + (lane & 3) * 4 + (jl & 1) * 2;
        float b0 = bias[c], b1 = bias[c + 1];
        acc[jl][0] = b0; acc[jl][1] = b1; acc[jl][2] = b0; acc[jl][3] = b1;
    }
}

// half of the fp16 GEMM: ks in [ks0, ks0+4)
__device__ __forceinline__ void gemm_half(uint32_t sb, uint32_t aOff, uint32_t bOff,
                                          int mt, int nh, int lane,
                                          float acc[4][4], int ks0) {
    const int j  = lane >> 3;
    const int rr = lane & 7;
    const uint32_t xo = (uint32_t)(rr << 2);
    const int rowA = mt * 16 + ((j & 1) << 3) + rr;
    const int rowB = ((j & 1) << 3) + rr;
    const uint32_t ksg = (uint32_t)((j >> 1) << 2);

    #pragma unroll
    for (int kk = 0; kk < 4; kk++) {
        const int ks = ks0 + kk;
        const uint32_t byte = (((uint32_t)(ks * 8) + ksg) ^ xo) << 2;
        uint32_t a[4];
        ldsm4(sb + aOff + (uint32_t)rowA * 256 + byte, a);
        #pragma unroll
        for (int p = 0; p < 2; p++) {
            const int np = nh * 2 + p;
            uint32_t b[4];
            ldsm4(sb + bOff + (uint32_t)(rowB + np * 16) * 256 + byte, b);
            mma_f16(acc[2*p],   a, b[0], b[2]);
            mma_f16(acc[2*p+1], a, b[1], b[3]);
        }
    }
}

// ==================== edge kernel (fp16, pipelined, TPB tiles) ====================
__device__ __forceinline__ void gather_half(
    const float4* x4, const float4* ea4, const float4* u4,
    const int* sDst, const int* sSrc, const int* sBB,
    long long eBase, int t, int it0, int tid, float4* gv)
{
    #pragma unroll
    for (int i = 0; i < 4; i++) {
        int idx = tid + (it0 + i) * THREADS;
        int r = idx >> 5, seg = idx & 31;
        int row = t * MTILE + r;
        int q = seg >> 3, f = seg & 7;
        const float4* p;
        if (q == 0)      p = x4  + (size_t)sDst[row] * 8 + f;
        else if (q == 1) p = x4  + (size_t)sSrc[row] * 8 + f;
        else if (q == 2) p = ea4 + (size_t)(eBase + row) * 8 + f;
        else             p = u4  + (size_t)sBB[row] * 8 + f;
        gv[i] = *p;
    }
}
__device__ __forceinline__ void stash_half(char* smem, uint32_t aOff,
                                           int it0, int tid, const float4* gv)
{
    #pragma unroll
    for (int i = 0; i < 4; i++) {
        int idx = tid + (it0 + i) * THREADS;
        int r = idx >> 5, seg = idx & 31;
        uint32_t w0 = (uint32_t)(seg * 2);
        *(uint32_t*)(smem + aOff + swz(r, w0))     = pack_f16(gv[i].x, gv[i].y);
        *(uint32_t*)(smem + aOff + swz(r, w0 + 1)) = pack_f16(gv[i].z, gv[i].w);
    }
}

__global__ void __launch_bounds__(THREADS, 2) edge_kernel(
    const float* __restrict__ x, const float* __restrict__ ea,
    const float* __restrict__ u, const float* __restrict__ b1)
{
    extern __shared__ char smem[];
    const uint32_t sb = smem_u32(smem);
    const int tid = threadIdx.x;
    const int lane = tid & 31, warp = tid >> 5;
    const int mt = warp >> 1, nh = warp & 1;

    int* sDst = (int*)(smem + E_DST);
    int* sSrc = (int*)(smem + E_SRC);
    int* sBB  = (int*)(smem + E_BB);

    const long long eBase = (long long)blockIdx.x * (MTILE * TPB);
    {   // all 512 indices for this block, one per thread
        int e = (int)eBase + tid;
        int s = g_src[e];
        sSrc[tid] = s;
        sDst[tid] = g_dst[e];
        sBB[tid]  = g_batch[s];
    }
    if (tid < OUTD) ((float*)(smem + E_BIAS))[tid] = b1[tid];
    {   // copy W1 fp16 (16KB) once per block
        const float4* w4 = (const float4*)g_w1f16;
        float4* d4 = (float4*)(smem + E_B);
        #pragma unroll
        for (int i = 0; i < 1024 / THREADS; i++)
            d4[tid + i * THREADS] = w4[tid + i * THREADS];
    }
    __syncthreads();   // indices visible

    const float4* x4  = (const float4*)x;
    const float4* ea4 = (const float4*)ea;
    const float4* u4  = (const float4*)u;

    // prologue: fill A0 for tile 0
    {
        float4 gv[4];
        gather_half(x4, ea4, u4, sDst, sSrc, sBB, eBase, 0, 0, tid, gv);
        stash_half(smem, E_A0, 0, tid, gv);
        gather_half(x4, ea4, u4, sDst, sSrc, sBB, eBase, 0, 4, tid, gv);
        stash_half(smem, E_A0, 4, tid, gv);
    }
    __syncthreads();

    const int ra = mt * 16 + (lane >> 2);
    const int rb = ra + 8;

    for (int t = 0; t < TPB; t++) {
        const uint32_t aCur = (t & 1) ? E_A1 : E_A0;
        const uint32_t aNxt = (t & 1) ? E_A0 : E_A1;

        float acc[4][4];
        init_acc((const float*)(smem + E_BIAS), nh, lane, acc);

        float4 gv[4];
        if (t + 1 < TPB)   // issue first half of next tile's gather
            gather_half(x4, ea4, u4, sDst, sSrc, sBB, eBase, t + 1, 0, tid, gv);

        gemm_half(sb, aCur, E_B, mt, nh, lane, acc, 0);   // hides LDG latency

        if (t + 1 < TPB) {
            stash_half(smem, aNxt, 0, tid, gv);
            gather_half(x4, ea4, u4, sDst, sSrc, sBB, eBase, t + 1, 4, tid, gv);
        }

        gemm_half(sb, aCur, E_B, mt, nh, lane, acc, 4);

        if (t + 1 < TPB)
            stash_half(smem, aNxt, 4, tid, gv);

        {   // relu + v4 scatter (bias already in acc)
            const int da = sDst[t * MTILE + ra];
            const int db = sDst[t * MTILE + rb];
            float* pa = g_agg + (size_t)da * OUTD + (lane & 3) * 4;
            float* pb = g_agg + (size_t)db * OUTD + (lane & 3) * 4;
            #pragma unroll
            for (int p = 0; p < 2; p++) {
                const int np = nh * 2 + p;
                red4(pa + np * 16,
                     fmaxf(acc[2*p][0], 0.f),   fmaxf(acc[2*p][1], 0.f),
                     fmaxf(acc[2*p+1][0], 0.f), fmaxf(acc[2*p+1][1], 0.f));
                red4(pb + np * 16,
                     fmaxf(acc[2*p][2], 0.f),   fmaxf(acc[2*p][3], 0.f),
                     fmaxf(acc[2*p+1][2], 0.f), fmaxf(acc[2*p+1][3], 0.f));
            }
        }
        __syncthreads();   // stash of next buffer visible; all reads of aCur done
    }
}

// ==================== node kernel (fp16 1-pass) ====================
__global__ void __launch_bounds__(THREADS, 2) node_kernel(
    const float* __restrict__ x, const float* __restrict__ u,
    const float* __restrict__ b2, float* __restrict__ out)
{
    extern __shared__ char smem[];
    const uint32_t sb = smem_u32(smem);
    const int tid = threadIdx.x;
    const long long n0 = (long long)blockIdx.x * MTILE;

    int* sBB = (int*)(smem + N_BB);
    if (tid < MTILE) {
        long long nn = n0 + tid;
        if (nn >= NNODES) nn = NNODES - 1;
        sBB[tid] = g_batch[nn];
    }
    if (tid < OUTD) ((float*)(smem + N_BIAS))[tid] = b2[tid];
    {   // copy W2 fp16
        const float4* w4 = (const float4*)g_w2f16;
        float4* d4 = (float4*)(smem + N_B);
        #pragma unroll
        for (int i = 0; i < 1024 / THREADS; i++)
            d4[tid + i * THREADS] = w4[tid + i * THREADS];
    }
    __syncthreads();

    {   // batched gather: full 128x32 float4 coverage = 8 iters/thread
        const float4* x4 = (const float4*)x;
        const float4* u4 = (const float4*)u;
        const float4* agg4 = (const float4*)g_agg;
        float4 gv[8];
        int gr[8], gseg[8];
        #pragma unroll
        for (int it = 0; it < 8; it++) {
            int idx = tid + it * THREADS;
            int r = idx >> 5, seg = idx & 31;
            gr[it] = r; gseg[it] = seg;
            long long nn = n0 + r;
            if (nn >= NNODES) nn = NNODES - 1;
            const float4* p;
            if (seg < 8)       p = x4   + (size_t)nn * 8 + seg;
            else if (seg < 24) p = agg4 + (size_t)nn * 16 + (seg - 8);
            else               p = u4   + (size_t)sBB[r] * 8 + (seg - 24);
            gv[it] = *p;
        }
        #pragma unroll
        for (int it = 0; it < 8; it++) {
            uint32_t w0 = (uint32_t)(gseg[it] * 2);
            *(uint32_t*)(smem + N_A + swz(gr[it], w0))     = pack_f16(gv[it].x, gv[it].y);
            *(uint32_t*)(smem + N_A + swz(gr[it], w0 + 1)) = pack_f16(gv[it].z, gv[it].w);
        }
    }
    __syncthreads();

    const int lane = tid & 31, warp = tid >> 5;
    const int mt = warp >> 1, nh = warp & 1;
    float acc[4][4];
    init_acc((const float*)(smem + N_BIAS), nh, lane, acc);

    gemm_half(sb, N_A, N_B, mt, nh, lane, acc, 0);
    gemm_half(sb, N_A, N_B, mt, nh, lane, acc, 4);

    {   // relu + float4 store
        long long ra = n0 + mt * 16 + (lane >> 2);
        long long rb = ra + 8;
        #pragma unroll
        for (int p = 0; p < 2; p++) {
            const int np = nh * 2 + p;
            int c = np * 16 + (lane & 3) * 4;
            if (ra < NNODES)
                *(float4*)(out + (size_t)ra * OUTD + c) = make_float4(
                    fmaxf(acc[2*p][0], 0.f),   fmaxf(acc[2*p][1], 0.f),
                    fmaxf(acc[2*p+1][0], 0.f), fmaxf(acc[2*p+1][1], 0.f));
            if (rb < NNODES)
                *(float4*)(out + (size_t)rb * OUTD + c) = make_float4(
                    fmaxf(acc[2*p][2], 0.f),   fmaxf(acc[2*p][3], 0.f),
                    fmaxf(acc[2*p+1][2], 0.f), fmaxf(acc[2*p+1][3], 0.f));
        }
    }
}

// ==================== launcher ====================
extern "C" void kernel_launch(void* const* d_in, const int* in_sizes, int n_in,
                              void* d_out, int out_size) {
    const float* x     = (const float*)d_in[0];
    const void*  ei    = d_in[1];
    const float* ea    = (const float*)d_in[2];
    const float* u     = (const float*)d_in[3];
    const void*  batch = d_in[4];
    const float* W1    = (const float*)d_in[5];
    const float* b1    = (const float*)d_in[6];
    const float* W2    = (const float*)d_in[7];
    const float* b2    = (const float*)d_in[8];
    float* out = (float*)d_out;

    cudaFuncSetAttribute(edge_kernel, cudaFuncAttributeMaxDynamicSharedMemorySize, E_SZ);
    cudaFuncSetAttribute(node_kernel, cudaFuncAttributeMaxDynamicSharedMemorySize, N_SZ);

    prep_kernel<<<1480, 256>>>(ei, batch, W1, W2);
    edge_kernel<<<EDGE_BLOCKS, THREADS, E_SZ>>>(x, ea, u, b1);
    node_kernel<<<NODE_BLOCKS, THREADS, N_SZ>>>(x, u, b2, out);
}